// round 14
// baseline (speedup 1.0000x reference)
#include <cuda_runtime.h>
#include <cuda_fp16.h>
#include <cstdint>

#define NEGC 1e9f

#define B_  32
#define T_  512
#define D_  256
#define O_  256
#define KF_ 8
#define G_  64

// ---------------- scratch ----------------
__device__ float g_R [B_ * O_ * T_];
__device__ float g_Q [B_ * O_ * T_];
__device__ float g_d1[B_ * T_];
__device__ float g_d2[B_ * T_];
__device__ float g_g1[B_ * T_];
__device__ float g_g2[B_ * T_];
__device__ float g_pq[B_ * T_];
__device__ float g_pv[B_ * T_];
__device__ int   g_len1[B_];
__device__ int   g_len2[B_];
__device__ int   g_jmin[B_];
__device__ int   g_imax[B_];

__device__ __half g_Uk[KF_ * T_ * O_];
__device__ __half g_Vk[KF_ * T_ * O_];
__device__ __half g_Rt[B_ * T_ * O_];
__device__ __half g_Qt[B_ * T_ * O_];
__device__ __half g_WRh[O_ * D_];
__device__ __half g_WQh[O_ * D_];
__device__ __half g_W2Rh[G_ * O_];
__device__ __half g_W2Qh[G_ * O_];
__device__ __half g_x0t[B_ * T_ * D_];
__device__ __half g_x1t[B_ * T_ * D_];
__device__ __half g_Ft [B_ * T_ * T_];
__device__ __half g_WRb[B_ * G_ * T_];
__device__ __half g_WQb[B_ * G_ * T_];

// =================== helpers ===================
__device__ __forceinline__ uint32_t smem_to_u32(const void* p) {
    uint32_t a;
    asm("{ .reg .u64 t; cvta.to.shared.u64 t, %1; cvt.u32.u64 %0, t; }" : "=r"(a) : "l"(p));
    return a;
}
__device__ __forceinline__ void ldsm4(uint32_t* r, uint32_t addr) {
    asm volatile("ldmatrix.sync.aligned.m8n8.x4.shared.b16 {%0,%1,%2,%3}, [%4];"
        : "=r"(r[0]), "=r"(r[1]), "=r"(r[2]), "=r"(r[3]) : "r"(addr));
}
__device__ __forceinline__ void mma16816h(float* d, const uint32_t* a,
                                          uint32_t b0, uint32_t b1) {
    asm volatile("mma.sync.aligned.m16n8k16.row.col.f32.f16.f16.f32 "
        "{%0,%1,%2,%3}, {%4,%5,%6,%7}, {%8,%9}, {%0,%1,%2,%3};"
        : "+f"(d[0]), "+f"(d[1]), "+f"(d[2]), "+f"(d[3])
        : "r"(a[0]), "r"(a[1]), "r"(a[2]), "r"(a[3]), "r"(b0), "r"(b1));
}
__device__ __forceinline__ void cpasync16(uint32_t dst, const void* src) {
    asm volatile("cp.async.cg.shared.global [%0], [%1], 16;" :: "r"(dst), "l"(src));
}
#define CP_COMMIT() asm volatile("cp.async.commit_group;" ::: "memory")
#define CP_WAIT(n)  asm volatile("cp.async.wait_group %0;" :: "n"(n) : "memory")

__device__ __forceinline__ uint32_t paddr(uint32_t row, uint32_t cb) {
    uint32_t pr = row >> 1;
    return pr * 128 + ((((row & 1) << 6) + cb) ^ ((pr & 7) << 4));
}

__device__ __forceinline__ void decode_mask(const unsigned char* q, const unsigned char* v,
                                            int i, bool& qv, bool& vv) {
    unsigned char b1 = q[1], b3 = q[3];
    int type = (b1 == 1) ? 0 : (b1 == 0x3F) ? 3 : (b3 == 0x3F) ? 2 : 1;
    switch (type) {
        case 0: qv = q[i] != 0;                            vv = v[i] != 0; break;
        case 1: qv = ((const int*)q)[i] != 0;              vv = ((const int*)v)[i] != 0; break;
        case 2: qv = ((const float*)q)[i] != 0.f;          vv = ((const float*)v)[i] != 0.f; break;
        default: qv = ((const unsigned short*)q)[i] != 0;  vv = ((const unsigned short*)v)[i] != 0; break;
    }
}

// ---------------- lens + mask decode (fused) ----------------
__global__ void lens_kernel(const unsigned char* __restrict__ q,
                            const unsigned char* __restrict__ v,
                            float* __restrict__ pq, float* __restrict__ pv,
                            int* __restrict__ len1, int* __restrict__ len2,
                            int* __restrict__ jmin, int* __restrict__ imax) {
    __shared__ int s1, s2;
    int b = blockIdx.x, t = threadIdx.x;
    if (t == 0) { s1 = 0; s2 = 0; }
    __syncthreads();
    bool qv, vv;
    decode_mask(q, v, b * T_ + t, qv, vv);
    pq[b * T_ + t] = qv ? 0.f : 1.f;
    pv[b * T_ + t] = vv ? 0.f : 1.f;
    unsigned m1 = __ballot_sync(0xffffffffu, qv);
    unsigned m2 = __ballot_sync(0xffffffffu, vv);
    if ((t & 31) == 0) { atomicAdd(&s1, __popc(m1)); atomicAdd(&s2, __popc(m2)); }
    __syncthreads();
    if (t == 0) {
        len1[b] = s1; len2[b] = s2;
        jmin[b] = s1 < s2 ? s1 : s2;
        imax[b] = s1 > s2 ? s1 : s2;
    }
}

// ---------------- U/V de-interleave + W/W2 conversion (fused) ----------------
__global__ void convs_kernel(const float* __restrict__ U, const float* __restrict__ V,
                             const float* __restrict__ WR, const float* __restrict__ WQ,
                             const float* __restrict__ W2R, const float* __restrict__ W2Q,
                             __half* __restrict__ Uo, __half* __restrict__ Vo,
                             __half* __restrict__ WRh, __half* __restrict__ WQh,
                             __half* __restrict__ W2Rh, __half* __restrict__ W2Qh) {
    int idx = blockIdx.x * blockDim.x + threadIdx.x;
    if (idx < KF_ * T_ * O_) {
        int k = idx >> 17;
        int m = idx & (T_ * O_ - 1);
        Uo[idx] = __float2half(U[m * KF_ + k]);
        Vo[idx] = __float2half(V[m * KF_ + k]);
    }
    if (idx < O_ * D_) {
        WRh[idx] = __float2half(WR[idx]);
        WQh[idx] = __float2half(WQ[idx]);
    }
    if (idx < G_ * O_) {
        W2Rh[idx] = __float2half(W2R[idx]);
        W2Qh[idx] = __float2half(W2Q[idx]);
    }
}

// ---------------- x transpose -> fp16 ----------------
__global__ void convX_kernel(const float* __restrict__ x0, const float* __restrict__ x1,
                             __half* __restrict__ x0t, __half* __restrict__ x1t) {
    __shared__ float tile[32][33];
    int zz = blockIdx.z;
    int b = zz & 31;
    bool is1 = (zz >> 5) != 0;
    const float* src = (is1 ? x1 : x0) + (long)b * D_ * T_;
    __half* dst = (is1 ? x1t : x0t) + (long)b * T_ * D_;
    int t0 = blockIdx.x * 32, k0 = blockIdx.y * 32;
    int tx = threadIdx.x, ty = threadIdx.y;
    #pragma unroll
    for (int r = 0; r < 4; r++)
        tile[ty + r * 8][tx] = src[(long)(k0 + ty + r * 8) * T_ + t0 + tx];
    __syncthreads();
    #pragma unroll
    for (int r = 0; r < 4; r++)
        dst[(long)(t0 + ty + r * 8) * D_ + k0 + tx] = __float2half(tile[tx][ty + r * 8]);
}

// ---------------- fp16 HMMA R/Q GEMM (merged R and Q via blockIdx.z) ----------------
__global__ __launch_bounds__(256) void gemm_rq_h_kernel(
    const __half* __restrict__ WRh, const __half* __restrict__ WQh,
    const __half* __restrict__ X0t, const __half* __restrict__ X1t,
    float* __restrict__ CR, float* __restrict__ CQ,
    __half* __restrict__ CRt, __half* __restrict__ CQt,
    const float* __restrict__ br, const float* __restrict__ bq,
    const float* __restrict__ pq, const float* __restrict__ pv,
    const int* __restrict__ l1, const int* __restrict__ l2) {
    __shared__ char gsm[49152];
    uint32_t sb = smem_to_u32(gsm);
    int z = blockIdx.z;
    int sel = z >> 5, b = z & 31;
    const __half* Wh = sel ? WQh : WRh;
    const __half* Xt = sel ? X1t : X0t;
    float* C = sel ? CQ : CR;
    __half* Ct = sel ? CQt : CRt;
    const float* bias = sel ? bq : br;
    const float* pad = sel ? pv : pq;
    const int* lenp = sel ? l2 : l1;

    int n0 = blockIdx.x * 128;
    int m0 = blockIdx.y * 64;
    int tid = threadIdx.x, lane = tid & 31, w = tid >> 5;
    int wi = w >> 2, wj = w & 3;
    int l16 = lane & 15, lh = lane >> 4;

    if (n0 >= lenp[b]) {
        float4 zf = make_float4(0.f, 0.f, 0.f, 0.f);
        #pragma unroll
        for (int e = 0; e < 8; e++) {
            int idx = tid + e * 256;
            int m = idx >> 5, nq = idx & 31;
            *reinterpret_cast<float4*>(&C[((long)b * O_ + m0 + m) * T_ + n0 + nq * 4]) = zf;
        }
        uint4 zh = make_uint4(0, 0, 0, 0);
        #pragma unroll
        for (int e = 0; e < 2; e++) {
            int idx = tid + e * 256;
            int n = idx >> 2, mq = idx & 3;
            *reinterpret_cast<uint4*>(&Ct[((long)b * T_ + n0 + n) * O_ + m0 + mq * 16]) = zh;
        }
        return;
    }

    const __half* Wb = Wh + (long)m0 * D_;
    const __half* Xb = Xt + ((long)b * T_ + n0) * D_;

    #pragma unroll
    for (int e = 0; e < 8; e++) {
        int idx = tid + e * 256;
        int ch = idx >> 8;
        int row = (idx & 255) >> 2;
        int cb = (idx & 3) * 16;
        cpasync16(sb + ch * 4096 + paddr(row, cb),
                  Wb + (long)row * D_ + ch * 32 + cb / 2);
    }
    CP_COMMIT();

    auto load_b = [&](int ch, int st) {
        #pragma unroll
        for (int e = 0; e < 2; e++) {
            int idx = tid + e * 256;
            int row = idx >> 2;
            int cb = (idx & 3) * 16;
            cpasync16(sb + 32768 + st * 8192 + paddr(row, cb),
                      Xb + (long)row * D_ + ch * 32 + cb / 2);
        }
    };
    load_b(0, 0);
    CP_COMMIT();

    float acc[32];
    #pragma unroll
    for (int i = 0; i < 32; i++) acc[i] = 0.f;

    for (int ch = 0; ch < 8; ch++) {
        int st = ch & 1;
        if (ch + 1 < 8) {
            load_b(ch + 1, st ^ 1);
            CP_COMMIT();
            CP_WAIT(1);
        } else {
            CP_WAIT(0);
        }
        __syncthreads();
        uint32_t abase = sb + ch * 4096;
        uint32_t bbase = sb + 32768 + st * 8192;
        #pragma unroll
        for (int os = 0; os < 2; os++) {
            uint32_t colb = (uint32_t)(os * 32 + lh * 16);
            uint32_t arow = (uint32_t)(wi * 32 + l16);
            uint32_t brow = (uint32_t)(wj * 32 + l16);
            uint32_t a0[4], a1[4], b0r[4], b1r[4];
            ldsm4(a0, abase + paddr(arow, colb));
            ldsm4(a1, abase + paddr(arow + 16, colb));
            ldsm4(b0r, bbase + paddr(brow, colb));
            ldsm4(b1r, bbase + paddr(brow + 16, colb));
            #pragma unroll
            for (int mt = 0; mt < 2; mt++) {
                const uint32_t* a = mt ? a1 : a0;
                #pragma unroll
                for (int nt = 0; nt < 4; nt++) {
                    const uint32_t* bb = (nt >> 1) ? b1r : b0r;
                    int s = nt & 1;
                    mma16816h(acc + (mt * 4 + nt) * 4, a, bb[s], bb[s + 2]);
                }
            }
        }
        __syncthreads();
    }

    __half* Cs = reinterpret_cast<__half*>(gsm);
    int r4 = lane >> 2, c2 = (lane & 3) * 2;
    #pragma unroll
    for (int mt = 0; mt < 2; mt++) {
        #pragma unroll
        for (int nt = 0; nt < 4; nt++) {
            float* d = acc + (mt * 4 + nt) * 4;
            #pragma unroll
            for (int half_ = 0; half_ < 2; half_++) {
                int row = wi * 32 + mt * 16 + r4 + half_ * 8;
                int col = wj * 32 + nt * 8 + c2;
                int m = m0 + row, n = n0 + col;
                float bi = bias[m];
                float v0 = fmaxf(d[half_ * 2 + 0] - NEGC * pad[b * T_ + n] + bi, 0.f);
                float v1 = fmaxf(d[half_ * 2 + 1] - NEGC * pad[b * T_ + n + 1] + bi, 0.f);
                float* dst = &C[((long)b * O_ + m) * T_ + n];
                dst[0] = v0; dst[1] = v1;
                Cs[row * 136 + col] = __float2half(v0);
                Cs[row * 136 + col + 1] = __float2half(v1);
            }
        }
    }
    __syncthreads();
    {
        int n = tid >> 1;
        int mh = (tid & 1) * 32;
        __half hbuf[32];
        #pragma unroll
        for (int mm = 0; mm < 32; mm++) hbuf[mm] = Cs[(mh + mm) * 136 + n];
        uint4* dst = reinterpret_cast<uint4*>(&Ct[((long)b * T_ + n0 + n) * O_ + m0 + mh]);
        const uint4* srcv = reinterpret_cast<const uint4*>(hbuf);
        dst[0] = srcv[0]; dst[1] = srcv[1]; dst[2] = srcv[2]; dst[3] = srcv[3];
    }
}

// ---------------- fp16 HMMA W2 GEMM (merged via blockIdx.z) ----------------
__global__ __launch_bounds__(256) void wgemm_h_kernel(
    const __half* __restrict__ W2Rh, const __half* __restrict__ W2Qh,
    const __half* __restrict__ Rt, const __half* __restrict__ Qt,
    __half* __restrict__ OutR, __half* __restrict__ OutQ) {
    __shared__ char gsm[49152];
    uint32_t sb = smem_to_u32(gsm);
    int z = blockIdx.z;
    int sel = z >> 5, b = z & 31;
    const __half* W2h = sel ? W2Qh : W2Rh;
    const __half* Xt = sel ? Qt : Rt;
    __half* Out = sel ? OutQ : OutR;

    int n0 = blockIdx.x * 128;
    int tid = threadIdx.x, lane = tid & 31, w = tid >> 5;
    int wi = w >> 2, wj = w & 3;
    int l16 = lane & 15, lh = lane >> 4;
    const __half* Xb = Xt + ((long)b * T_ + n0) * O_;

    #pragma unroll
    for (int e = 0; e < 8; e++) {
        int idx = tid + e * 256;
        int ch = idx >> 8;
        int row = (idx & 255) >> 2;
        int cb = (idx & 3) * 16;
        cpasync16(sb + ch * 4096 + paddr(row, cb),
                  W2h + (long)row * O_ + ch * 32 + cb / 2);
    }
    CP_COMMIT();

    auto load_b = [&](int ch, int st) {
        #pragma unroll
        for (int e = 0; e < 2; e++) {
            int idx = tid + e * 256;
            int row = idx >> 2;
            int cb = (idx & 3) * 16;
            cpasync16(sb + 32768 + st * 8192 + paddr(row, cb),
                      Xb + (long)row * O_ + ch * 32 + cb / 2);
        }
    };
    load_b(0, 0);
    CP_COMMIT();

    float acc[32];
    #pragma unroll
    for (int i = 0; i < 32; i++) acc[i] = 0.f;

    for (int ch = 0; ch < 8; ch++) {
        int st = ch & 1;
        if (ch + 1 < 8) {
            load_b(ch + 1, st ^ 1);
            CP_COMMIT();
            CP_WAIT(1);
        } else {
            CP_WAIT(0);
        }
        __syncthreads();
        uint32_t abase = sb + ch * 4096;
        uint32_t bbase = sb + 32768 + st * 8192;
        #pragma unroll
        for (int os = 0; os < 2; os++) {
            uint32_t colb = (uint32_t)(os * 32 + lh * 16);
            uint32_t arow = (uint32_t)(wi * 32 + l16);
            uint32_t brow = (uint32_t)(wj * 32 + l16);
            uint32_t a0[4], a1[4], b0r[4], b1r[4];
            ldsm4(a0, abase + paddr(arow, colb));
            ldsm4(a1, abase + paddr(arow + 16, colb));
            ldsm4(b0r, bbase + paddr(brow, colb));
            ldsm4(b1r, bbase + paddr(brow + 16, colb));
            #pragma unroll
            for (int mt = 0; mt < 2; mt++) {
                const uint32_t* a = mt ? a1 : a0;
                #pragma unroll
                for (int nt = 0; nt < 4; nt++) {
                    const uint32_t* bb = (nt >> 1) ? b1r : b0r;
                    int s = nt & 1;
                    mma16816h(acc + (mt * 4 + nt) * 4, a, bb[s], bb[s + 2]);
                }
            }
        }
        __syncthreads();
    }

    int r4 = lane >> 2, c2 = (lane & 3) * 2;
    #pragma unroll
    for (int mt = 0; mt < 2; mt++) {
        #pragma unroll
        for (int nt = 0; nt < 4; nt++) {
            float* d = acc + (mt * 4 + nt) * 4;
            #pragma unroll
            for (int half_ = 0; half_ < 2; half_++) {
                int g = wi * 32 + mt * 16 + r4 + half_ * 8;
                int t = n0 + wj * 32 + nt * 8 + c2;
                __half2 v = __floats2half2_rn(d[half_ * 2], d[half_ * 2 + 1]);
                *reinterpret_cast<__half2*>(&Out[((long)b * G_ + g) * T_ + t]) = v;
            }
        }
    }
}

// ======================= fp16 HMMA F kernel: 128i x 128j tile, 512 threads =======================
// SMEM: A ring 2 stages x 2 arr x 8KB = 32KB at 0; B persistent 2 arr x 64KB at 32768.
#define FS_B 32768
#define FS_TOTAL 163840

__global__ __launch_bounds__(512, 1) void f_mma_kernel(
    const __half* __restrict__ Uk, const __half* __restrict__ Vk,
    const __half* __restrict__ Rt, const __half* __restrict__ Qt,
    __half* __restrict__ Ft, const int* __restrict__ jmin, const int* __restrict__ imax) {
    extern __shared__ char sm[];
    uint32_t sb = smem_to_u32(sm);
    int tid = threadIdx.x, lane = tid & 31, w = tid >> 5;
    int wi = w >> 2, wj = w & 3;
    int b = blockIdx.z, i0 = blockIdx.y * 128, j0 = blockIdx.x * 128;
    int l16 = lane & 15, lh = lane >> 4;

    if (i0 >= imax[b]) return;

    if (j0 >= jmin[b]) {
        uint4 z4 = make_uint4(0, 0, 0, 0);
        #pragma unroll
        for (int e = 0; e < 4; e++) {
            int idx = tid + e * 512;            // 0..2047
            int j = idx >> 4, icol = (idx & 15) * 8;
            *reinterpret_cast<uint4*>(&Ft[((long)b * T_ + j0 + j) * T_ + i0 + icol]) = z4;
        }
        return;
    }

    const __half* apt[2] = {Uk, Vk};
    const __half* bpt[2] = {Rt, Qt};

    // B persistent: 2 arr x [128j][256o], chunked per 32 o (8KB chunks)
    #pragma unroll
    for (int arr = 0; arr < 2; arr++) {
        const __half* src = bpt[arr] + ((long)b * T_ + j0) * O_;
        #pragma unroll
        for (int e = 0; e < 8; e++) {
            int idx = tid + e * 512;            // 0..4095
            int ch = idx >> 9;
            int row = (idx & 511) >> 2;
            int cb = (idx & 3) * 16;
            cpasync16(sb + FS_B + arr * 65536 + ch * 8192 + paddr(row, cb),
                      src + (long)row * O_ + ch * 32 + cb / 2);
        }
    }
    CP_COMMIT();

    auto load_a = [&](int cu, int st) {
        int k = cu >> 3, ch = cu & 7;
        #pragma unroll
        for (int arr = 0; arr < 2; arr++) {
            const __half* src = apt[arr] + ((long)k * T_ + i0) * O_ + ch * 32;
            int row = tid >> 2, cb = (tid & 3) * 16;
            cpasync16(sb + st * 16384 + arr * 8192 + paddr(row, cb),
                      src + (long)row * O_ + cb / 2);
        }
    };

    load_a(0, 0);
    CP_COMMIT();

    float f[32], d1[32], d2[32];
    #pragma unroll
    for (int i = 0; i < 32; i++) { f[i] = 0.f; d1[i] = 0.f; d2[i] = 0.f; }

    for (int cu = 0; cu < 64; cu++) {
        int st = cu & 1, ch = cu & 7;
        if (cu + 1 < 64) {
            load_a(cu + 1, (cu + 1) & 1);
            CP_COMMIT();
            CP_WAIT(1);
        } else {
            CP_WAIT(0);
        }
        __syncthreads();

        uint32_t abase = sb + st * 16384;
        #pragma unroll
        for (int os = 0; os < 2; os++) {
            uint32_t colb = (uint32_t)(os * 32 + lh * 16);
            uint32_t arow = (uint32_t)(wi * 32 + l16);
            uint32_t brow = (uint32_t)(wj * 32 + l16);
            {
                uint32_t a0[4], a1[4], b0r[4], b1r[4];
                ldsm4(a0, abase + 0 * 8192 + paddr(arow, colb));
                ldsm4(a1, abase + 0 * 8192 + paddr(arow + 16, colb));
                uint32_t bb0 = sb + FS_B + 0 * 65536 + ch * 8192;
                ldsm4(b0r, bb0 + paddr(brow, colb));
                ldsm4(b1r, bb0 + paddr(brow + 16, colb));
                #pragma unroll
                for (int mt = 0; mt < 2; mt++) {
                    const uint32_t* a = mt ? a1 : a0;
                    #pragma unroll
                    for (int nt = 0; nt < 4; nt++) {
                        const uint32_t* bb = (nt >> 1) ? b1r : b0r;
                        int s = nt & 1;
                        mma16816h(d1 + (mt * 4 + nt) * 4, a, bb[s], bb[s + 2]);
                    }
                }
            }
            {
                uint32_t a0[4], a1[4], b0r[4], b1r[4];
                ldsm4(a0, abase + 1 * 8192 + paddr(arow, colb));
                ldsm4(a1, abase + 1 * 8192 + paddr(arow + 16, colb));
                uint32_t bb1 = sb + FS_B + 1 * 65536 + ch * 8192;
                ldsm4(b0r, bb1 + paddr(brow, colb));
                ldsm4(b1r, bb1 + paddr(brow + 16, colb));
                #pragma unroll
                for (int mt = 0; mt < 2; mt++) {
                    const uint32_t* a = mt ? a1 : a0;
                    #pragma unroll
                    for (int nt = 0; nt < 4; nt++) {
                        const uint32_t* bb = (nt >> 1) ? b1r : b0r;
                        int s = nt & 1;
                        mma16816h(d2 + (mt * 4 + nt) * 4, a, bb[s], bb[s + 2]);
                    }
                }
            }
        }
        if (ch == 7) {
            #pragma unroll
            for (int i = 0; i < 32; i++) {
                f[i] += d1[i] * d2[i];
                d1[i] = 0.f; d2[i] = 0.f;
            }
        }
        __syncthreads();
    }

    // stage fp16 [128 i][136 j] into B SMEM region (free now), transposed write
    __half* Fs16 = reinterpret_cast<__half*>(sm + FS_B);
    int r4 = lane >> 2, c2 = (lane & 3) * 2;
    #pragma unroll
    for (int mt = 0; mt < 2; mt++) {
        #pragma unroll
        for (int nt = 0; nt < 4; nt++) {
            float* d = f + (mt * 4 + nt) * 4;
            #pragma unroll
            for (int hh = 0; hh < 2; hh++) {
                int i_l = wi * 32 + mt * 16 + r4 + hh * 8;
                int j_l = wj * 32 + nt * 8 + c2;
                *reinterpret_cast<__half2*>(&Fs16[i_l * 136 + j_l]) =
                    __floats2half2_rn(d[hh * 2], d[hh * 2 + 1]);
            }
        }
    }
    __syncthreads();
    #pragma unroll
    for (int e = 0; e < 4; e++) {
        int idx = tid + e * 512;                // 0..2047
        int j = idx >> 4, icol = (idx & 15) * 8;
        __half hbuf[8];
        #pragma unroll
        for (int ii = 0; ii < 8; ii++) hbuf[ii] = Fs16[(icol + ii) * 136 + j];
        *reinterpret_cast<uint4*>(&Ft[((long)b * T_ + j0 + j) * T_ + i0 + icol]) =
            *reinterpret_cast<const uint4*>(hbuf);
    }
}

// ---------------- fp16 HMMA fused M + d kernel (merged via blockIdx.z) ----------------
__global__ __launch_bounds__(128) void md_h_kernel(
    const __half* __restrict__ WRb, const __half* __restrict__ WQb,
    const __half* __restrict__ Ft,
    const float* __restrict__ wmv, const float* __restrict__ wmq,
    const float* __restrict__ pq, const float* __restrict__ pv,
    float* __restrict__ d1, float* __restrict__ d2,
    const int* __restrict__ l1, const int* __restrict__ l2) {
    __shared__ char msm[16384];
    __shared__ float red[64][65];
    __shared__ float p2[2][64];
    uint32_t sb = smem_to_u32(msm);
    int sel = blockIdx.z;
    int b = blockIdx.y, c0 = blockIdx.x * 64;
    const __half* Bias = sel ? WQb : WRb;
    const __half* Mul  = sel ? WRb : WQb;
    const float* wv = sel ? wmq : wmv;
    const float* pad = sel ? pv : pq;
    float* d = sel ? d2 : d1;
    const int* lencol = sel ? l2 : l1;
    const int* lenmul = sel ? l1 : l2;

    int tid = threadIdx.x, lane = tid & 31, w_ = tid >> 5;
    int wg = w_ >> 1, wc = w_ & 1;
    int l16 = lane & 15, lh = lane >> 4;

    if (c0 >= lencol[b]) {
        if (tid < 64) d[b * T_ + c0 + tid] = -NEGC;
        return;
    }
    int nch = ((lenmul[b] + 31) & ~31) >> 5;
    const __half* Mb = Mul + (long)b * G_ * T_;
    const __half* Fb = Ft + ((long)b * T_ + c0) * T_;

    auto load_ch = [&](int ch, int st) {
        #pragma unroll
        for (int e = 0; e < 2; e++) {
            int idx = tid + e * 128;
            int row = idx >> 2, cb = (idx & 3) * 16;
            cpasync16(sb + st * 8192 + paddr(row, cb), Mb + (long)row * T_ + ch * 32 + cb / 2);
        }
        #pragma unroll
        for (int e = 0; e < 2; e++) {
            int idx = tid + e * 128;
            int row = idx >> 2, cb = (idx & 3) * 16;
            cpasync16(sb + st * 8192 + 4096 + paddr(row, cb), Fb + (long)row * T_ + ch * 32 + cb / 2);
        }
    };
    load_ch(0, 0);
    CP_COMMIT();

    float acc[32];
    #pragma unroll
    for (int i = 0; i < 32; i++) acc[i] = 0.f;

    for (int ch = 0; ch < nch; ch++) {
        int st = ch & 1;
        if (ch + 1 < nch) {
            load_ch(ch + 1, st ^ 1);
            CP_COMMIT();
            CP_WAIT(1);
        } else {
            CP_WAIT(0);
        }
        __syncthreads();
        uint32_t ab = sb + st * 8192, bb_ = ab + 4096;
        #pragma unroll
        for (int os = 0; os < 2; os++) {
            uint32_t colb = (uint32_t)(os * 32 + lh * 16);
            uint32_t arow = (uint32_t)(wg * 32 + l16);
            uint32_t brow = (uint32_t)(wc * 32 + l16);
            uint32_t a0[4], a1[4], b0r[4], b1r[4];
            ldsm4(a0, ab + paddr(arow, colb));
            ldsm4(a1, ab + paddr(arow + 16, colb));
            ldsm4(b0r, bb_ + paddr(brow, colb));
            ldsm4(b1r, bb_ + paddr(brow + 16, colb));
            #pragma unroll
            for (int mt = 0; mt < 2; mt++) {
                const uint32_t* a = mt ? a1 : a0;
                #pragma unroll
                for (int nt = 0; nt < 4; nt++) {
                    const uint32_t* bb = (nt >> 1) ? b1r : b0r;
                    int s = nt & 1;
                    mma16816h(acc + (mt * 4 + nt) * 4, a, bb[s], bb[s + 2]);
                }
            }
        }
        __syncthreads();
    }

    int r4 = lane >> 2, c2 = (lane & 3) * 2;
    #pragma unroll
    for (int mt = 0; mt < 2; mt++) {
        #pragma unroll
        for (int nt = 0; nt < 4; nt++) {
            float* dd = acc + (mt * 4 + nt) * 4;
            #pragma unroll
            for (int hh = 0; hh < 2; hh++) {
                int g = wg * 32 + mt * 16 + r4 + hh * 8;
                int col = wc * 32 + nt * 8 + c2;
                float wgt = wv[g];
                float bi0 = __half2float(Bias[(long)b * G_ * T_ + g * T_ + c0 + col]);
                float bi1 = __half2float(Bias[(long)b * G_ * T_ + g * T_ + c0 + col + 1]);
                red[g][col]     = wgt * fmaxf(dd[hh * 2 + 0] + bi0, 0.f);
                red[g][col + 1] = wgt * fmaxf(dd[hh * 2 + 1] + bi1, 0.f);
            }
        }
    }
    __syncthreads();
    {
        int col = tid & 63, h = tid >> 6;
        float s = 0.f;
        #pragma unroll
        for (int g = 0; g < 32; g++) s += red[h * 32 + g][col];
        p2[h][col] = s;
    }
    __syncthreads();
    if (tid < 64)
        d[b * T_ + c0 + tid] = p2[0][tid] + p2[1][tid] - NEGC * pad[b * T_ + c0 + tid];
}

// ---------------- softmax ----------------
__global__ void softmax_kernel(const float* __restrict__ d1, const float* __restrict__ d2,
                               float* __restrict__ g1, float* __restrict__ g2) {
    int b = blockIdx.x;
    const float* d = blockIdx.y ? d2 : d1;
    float* g = blockIdx.y ? g2 : g1;
    int t = threadIdx.x;
    float v = d[b * T_ + t];
    __shared__ float red[16];
    float m = v;
    #pragma unroll
    for (int o = 16; o; o >>= 1) m = fmaxf(m, __shfl_xor_sync(0xffffffffu, m, o));
    if ((t & 31) == 0) red[t >> 5] = m;
    __syncthreads();
    if (t < 32) {
        float x = (t < 16) ? red[t] : -3.4e38f;
        #pragma unroll
        for (int o = 8; o; o >>= 1) x = fmaxf(x, __shfl_xor_sync(0xffffffffu, x, o));
        if (t == 0) red[0] = x;
    }
    __syncthreads();
    float mx = red[0];
    __syncthreads();
    float e = expf(v - mx);
    float s = e;
    #pragma unroll
    for (int o = 16; o; o >>= 1) s += __shfl_xor_sync(0xffffffffu, s, o);
    if ((t & 31) == 0) red[t >> 5] = s;
    __syncthreads();
    if (t < 32) {
        float x = (t < 16) ? red[t] : 0.f;
        #pragma unroll
        for (int o = 8; o; o >>= 1) x += __shfl_xor_sync(0xffffffffu, x, o);
        if (t == 0) red[0] = x;
    }
    __syncthreads();
    g[b * T_ + t] = e / red[0];
}

// ---------------- final reduction ----------------
__global__ void final_kernel(const float* __restrict__ R, const float* __restrict__ Q,
                             const float* __restrict__ gv, const float* __restrict__ gq,
                             float* __restrict__ out) {
    int b = blockIdx.x;
    __shared__ float sgv[T_], sgq[T_];
    int tid = threadIdx.x;
    sgv[tid] = gv[b * T_ + tid];
    sgq[tid] = gq[b * T_ + tid];
    __syncthreads();
    int o = tid & 255;
    int h = tid >> 8;
    const float* Rb = R + (long)b * O_ * T_;
    const float* Qb = Q + (long)b * O_ * T_;
    float tr = 0.f, lg = 0.f;
    #pragma unroll 4
    for (int t = h * 256; t < h * 256 + 256; t++) {
        tr += sgv[t] * Rb[t * O_ + o];
        lg += sgq[t] * Qb[t * O_ + o];
    }
    __shared__ float str[2][256], slg[2][256];
    str[h][o] = tr;
    slg[h][o] = lg;
    __syncthreads();
    if (h == 0) out[b * O_ + o] = (str[0][o] + str[1][o]) * (slg[0][o] + slg[1][o]);
}

// ---------------- launcher ----------------
extern "C" void kernel_launch(void* const* d_in, const int* in_sizes, int n_in,
                              void* d_out, int out_size) {
    const float* x0  = (const float*)d_in[0];
    const float* x1  = (const float*)d_in[1];
    const unsigned char* qm = (const unsigned char*)d_in[2];
    const unsigned char* vm = (const unsigned char*)d_in[3];
    const float* W_R = (const float*)d_in[4];
    const float* W_Q = (const float*)d_in[5];
    const float* br  = (const float*)d_in[6];
    const float* bq  = (const float*)d_in[7];
    const float* U   = (const float*)d_in[8];
    const float* V   = (const float*)d_in[9];
    const float* W2R = (const float*)d_in[10];
    const float* W2Q = (const float*)d_in[11];
    const float* wmv = (const float*)d_in[12];
    const float* wmq = (const float*)d_in[13];
    float* out = (float*)d_out;

    float *pR, *pQ, *pd1, *pd2, *pg1, *pg2, *ppq, *ppv;
    int *pl1, *pl2, *pjm, *pim;
    __half *pUk, *pVk, *pRt, *pQt, *pWRh, *pWQh, *pW2Rh, *pW2Qh, *px0t, *px1t, *pFt, *pWRb, *pWQb;
    cudaGetSymbolAddress((void**)&pR,  g_R);
    cudaGetSymbolAddress((void**)&pQ,  g_Q);
    cudaGetSymbolAddress((void**)&pd1, g_d1);
    cudaGetSymbolAddress((void**)&pd2, g_d2);
    cudaGetSymbolAddress((void**)&pg1, g_g1);
    cudaGetSymbolAddress((void**)&pg2, g_g2);
    cudaGetSymbolAddress((void**)&ppq, g_pq);
    cudaGetSymbolAddress((void**)&ppv, g_pv);
    cudaGetSymbolAddress((void**)&pl1, g_len1);
    cudaGetSymbolAddress((void**)&pl2, g_len2);
    cudaGetSymbolAddress((void**)&pjm, g_jmin);
    cudaGetSymbolAddress((void**)&pim, g_imax);
    cudaGetSymbolAddress((void**)&pUk, g_Uk);
    cudaGetSymbolAddress((void**)&pVk, g_Vk);
    cudaGetSymbolAddress((void**)&pRt, g_Rt);
    cudaGetSymbolAddress((void**)&pQt, g_Qt);
    cudaGetSymbolAddress((void**)&pWRh, g_WRh);
    cudaGetSymbolAddress((void**)&pWQh, g_WQh);
    cudaGetSymbolAddress((void**)&pW2Rh, g_W2Rh);
    cudaGetSymbolAddress((void**)&pW2Qh, g_W2Qh);
    cudaGetSymbolAddress((void**)&px0t, g_x0t);
    cudaGetSymbolAddress((void**)&px1t, g_x1t);
    cudaGetSymbolAddress((void**)&pFt, g_Ft);
    cudaGetSymbolAddress((void**)&pWRb, g_WRb);
    cudaGetSymbolAddress((void**)&pWQb, g_WQb);

    static bool attr_done = false;
    if (!attr_done) {
        cudaFuncSetAttribute(f_mma_kernel, cudaFuncAttributeMaxDynamicSharedMemorySize, FS_TOTAL);
        attr_done = true;
    }

    lens_kernel<<<B_, T_>>>(qm, vm, ppq, ppv, pl1, pl2, pjm, pim);
    convs_kernel<<<(KF_ * T_ * O_ + 255) / 256, 256>>>(
        U, V, W_R, W_Q, W2R, W2Q, pUk, pVk, pWRh, pWQh, pW2Rh, pW2Qh);
    convX_kernel<<<dim3(T_ / 32, D_ / 32, 2 * B_), dim3(32, 8)>>>(x0, x1, px0t, px1t);

    gemm_rq_h_kernel<<<dim3(T_ / 128, O_ / 64, 2 * B_), 256>>>(
        pWRh, pWQh, px0t, px1t, pR, pQ, pRt, pQt, br, bq, ppq, ppv, pl1, pl2);

    f_mma_kernel<<<dim3(T_ / 128, T_ / 128, B_), 512, FS_TOTAL>>>(
        pUk, pVk, pRt, pQt, pFt, pjm, pim);

    wgemm_h_kernel<<<dim3(T_ / 128, 1, 2 * B_), 256>>>(
        pW2Rh, pW2Qh, pRt, pQt, pWRb, pWQb);

    md_h_kernel<<<dim3(T_ / 64, B_, 2), 128>>>(
        pWRb, pWQb, pFt, wmv, wmq, ppq, ppv, pd1, pd2, pl1, pl2);

    softmax_kernel<<<dim3(B_, 2), T_>>>(pd1, pd2, pg1, pg2);

    final_kernel<<<B_, T_>>>(pR, pQ, pg1, pg2, out);
}

// round 15
// speedup vs baseline: 1.1201x; 1.1201x over previous
#include <cuda_runtime.h>
#include <cuda_fp16.h>
#include <cstdint>

#define NEGC 1e9f

#define B_  32
#define T_  512
#define D_  256
#define O_  256
#define KF_ 8
#define G_  64

// ---------------- scratch ----------------
__device__ float g_R [B_ * O_ * T_];
__device__ float g_Q [B_ * O_ * T_];
__device__ float g_d1[B_ * T_];
__device__ float g_d2[B_ * T_];
__device__ float g_g1[B_ * T_];
__device__ float g_g2[B_ * T_];
__device__ float g_pq[B_ * T_];
__device__ float g_pv[B_ * T_];
__device__ int   g_len1[B_];
__device__ int   g_len2[B_];
__device__ int   g_jmin[B_];
__device__ int   g_imax[B_];

__device__ __half g_Uk[KF_ * T_ * O_];
__device__ __half g_Vk[KF_ * T_ * O_];
__device__ __half g_Rt[B_ * T_ * O_];
__device__ __half g_Qt[B_ * T_ * O_];
__device__ __half g_WRh[O_ * D_];
__device__ __half g_WQh[O_ * D_];
__device__ __half g_W2Rh[G_ * O_];
__device__ __half g_W2Qh[G_ * O_];
__device__ __half g_x0t[B_ * T_ * D_];
__device__ __half g_x1t[B_ * T_ * D_];
__device__ __half g_Ft [B_ * T_ * T_];
__device__ __half g_WRb[B_ * G_ * T_];
__device__ __half g_WQb[B_ * G_ * T_];

// =================== helpers ===================
__device__ __forceinline__ uint32_t smem_to_u32(const void* p) {
    uint32_t a;
    asm("{ .reg .u64 t; cvta.to.shared.u64 t, %1; cvt.u32.u64 %0, t; }" : "=r"(a) : "l"(p));
    return a;
}
__device__ __forceinline__ void ldsm4(uint32_t* r, uint32_t addr) {
    asm volatile("ldmatrix.sync.aligned.m8n8.x4.shared.b16 {%0,%1,%2,%3}, [%4];"
        : "=r"(r[0]), "=r"(r[1]), "=r"(r[2]), "=r"(r[3]) : "r"(addr));
}
__device__ __forceinline__ void mma16816h(float* d, const uint32_t* a,
                                          uint32_t b0, uint32_t b1) {
    asm volatile("mma.sync.aligned.m16n8k16.row.col.f32.f16.f16.f32 "
        "{%0,%1,%2,%3}, {%4,%5,%6,%7}, {%8,%9}, {%0,%1,%2,%3};"
        : "+f"(d[0]), "+f"(d[1]), "+f"(d[2]), "+f"(d[3])
        : "r"(a[0]), "r"(a[1]), "r"(a[2]), "r"(a[3]), "r"(b0), "r"(b1));
}
__device__ __forceinline__ void cpasync16(uint32_t dst, const void* src) {
    asm volatile("cp.async.cg.shared.global [%0], [%1], 16;" :: "r"(dst), "l"(src));
}
#define CP_COMMIT() asm volatile("cp.async.commit_group;" ::: "memory")
#define CP_WAIT(n)  asm volatile("cp.async.wait_group %0;" :: "n"(n) : "memory")

__device__ __forceinline__ uint32_t paddr(uint32_t row, uint32_t cb) {
    uint32_t pr = row >> 1;
    return pr * 128 + ((((row & 1) << 6) + cb) ^ ((pr & 7) << 4));
}

__device__ __forceinline__ void decode_mask(const unsigned char* q, const unsigned char* v,
                                            int i, bool& qv, bool& vv) {
    unsigned char b1 = q[1], b3 = q[3];
    int type = (b1 == 1) ? 0 : (b1 == 0x3F) ? 3 : (b3 == 0x3F) ? 2 : 1;
    switch (type) {
        case 0: qv = q[i] != 0;                            vv = v[i] != 0; break;
        case 1: qv = ((const int*)q)[i] != 0;              vv = ((const int*)v)[i] != 0; break;
        case 2: qv = ((const float*)q)[i] != 0.f;          vv = ((const float*)v)[i] != 0.f; break;
        default: qv = ((const unsigned short*)q)[i] != 0;  vv = ((const unsigned short*)v)[i] != 0; break;
    }
}

// ---------------- lens + mask decode (fused) ----------------
__global__ void lens_kernel(const unsigned char* __restrict__ q,
                            const unsigned char* __restrict__ v,
                            float* __restrict__ pq, float* __restrict__ pv,
                            int* __restrict__ len1, int* __restrict__ len2,
                            int* __restrict__ jmin, int* __restrict__ imax) {
    __shared__ int s1, s2;
    int b = blockIdx.x, t = threadIdx.x;
    if (t == 0) { s1 = 0; s2 = 0; }
    __syncthreads();
    bool qv, vv;
    decode_mask(q, v, b * T_ + t, qv, vv);
    pq[b * T_ + t] = qv ? 0.f : 1.f;
    pv[b * T_ + t] = vv ? 0.f : 1.f;
    unsigned m1 = __ballot_sync(0xffffffffu, qv);
    unsigned m2 = __ballot_sync(0xffffffffu, vv);
    if ((t & 31) == 0) { atomicAdd(&s1, __popc(m1)); atomicAdd(&s2, __popc(m2)); }
    __syncthreads();
    if (t == 0) {
        len1[b] = s1; len2[b] = s2;
        jmin[b] = s1 < s2 ? s1 : s2;
        imax[b] = s1 > s2 ? s1 : s2;
    }
}

// ---------------- U/V de-interleave + W/W2 conversion (fused) ----------------
__global__ void convs_kernel(const float* __restrict__ U, const float* __restrict__ V,
                             const float* __restrict__ WR, const float* __restrict__ WQ,
                             const float* __restrict__ W2R, const float* __restrict__ W2Q,
                             __half* __restrict__ Uo, __half* __restrict__ Vo,
                             __half* __restrict__ WRh, __half* __restrict__ WQh,
                             __half* __restrict__ W2Rh, __half* __restrict__ W2Qh) {
    int idx = blockIdx.x * blockDim.x + threadIdx.x;
    if (idx < KF_ * T_ * O_) {
        int k = idx >> 17;
        int m = idx & (T_ * O_ - 1);
        Uo[idx] = __float2half(U[m * KF_ + k]);
        Vo[idx] = __float2half(V[m * KF_ + k]);
    }
    if (idx < O_ * D_) {
        WRh[idx] = __float2half(WR[idx]);
        WQh[idx] = __float2half(WQ[idx]);
    }
    if (idx < G_ * O_) {
        W2Rh[idx] = __float2half(W2R[idx]);
        W2Qh[idx] = __float2half(W2Q[idx]);
    }
}

// ---------------- x transpose -> fp16 ----------------
__global__ void convX_kernel(const float* __restrict__ x0, const float* __restrict__ x1,
                             __half* __restrict__ x0t, __half* __restrict__ x1t) {
    __shared__ float tile[32][33];
    int zz = blockIdx.z;
    int b = zz & 31;
    bool is1 = (zz >> 5) != 0;
    const float* src = (is1 ? x1 : x0) + (long)b * D_ * T_;
    __half* dst = (is1 ? x1t : x0t) + (long)b * T_ * D_;
    int t0 = blockIdx.x * 32, k0 = blockIdx.y * 32;
    int tx = threadIdx.x, ty = threadIdx.y;
    #pragma unroll
    for (int r = 0; r < 4; r++)
        tile[ty + r * 8][tx] = src[(long)(k0 + ty + r * 8) * T_ + t0 + tx];
    __syncthreads();
    #pragma unroll
    for (int r = 0; r < 4; r++)
        dst[(long)(t0 + ty + r * 8) * D_ + k0 + tx] = __float2half(tile[tx][ty + r * 8]);
}

// ---------------- fp16 HMMA R/Q GEMM (merged R and Q via blockIdx.z) ----------------
__global__ __launch_bounds__(256) void gemm_rq_h_kernel(
    const __half* __restrict__ WRh, const __half* __restrict__ WQh,
    const __half* __restrict__ X0t, const __half* __restrict__ X1t,
    float* __restrict__ CR, float* __restrict__ CQ,
    __half* __restrict__ CRt, __half* __restrict__ CQt,
    const float* __restrict__ br, const float* __restrict__ bq,
    const float* __restrict__ pq, const float* __restrict__ pv,
    const int* __restrict__ l1, const int* __restrict__ l2) {
    __shared__ char gsm[49152];
    uint32_t sb = smem_to_u32(gsm);
    int z = blockIdx.z;
    int sel = z >> 5, b = z & 31;
    const __half* Wh = sel ? WQh : WRh;
    const __half* Xt = sel ? X1t : X0t;
    float* C = sel ? CQ : CR;
    __half* Ct = sel ? CQt : CRt;
    const float* bias = sel ? bq : br;
    const float* pad = sel ? pv : pq;
    const int* lenp = sel ? l2 : l1;

    int n0 = blockIdx.x * 128;
    int m0 = blockIdx.y * 64;
    int tid = threadIdx.x, lane = tid & 31, w = tid >> 5;
    int wi = w >> 2, wj = w & 3;
    int l16 = lane & 15, lh = lane >> 4;

    if (n0 >= lenp[b]) {
        float4 zf = make_float4(0.f, 0.f, 0.f, 0.f);
        #pragma unroll
        for (int e = 0; e < 8; e++) {
            int idx = tid + e * 256;
            int m = idx >> 5, nq = idx & 31;
            *reinterpret_cast<float4*>(&C[((long)b * O_ + m0 + m) * T_ + n0 + nq * 4]) = zf;
        }
        uint4 zh = make_uint4(0, 0, 0, 0);
        #pragma unroll
        for (int e = 0; e < 2; e++) {
            int idx = tid + e * 256;
            int n = idx >> 2, mq = idx & 3;
            *reinterpret_cast<uint4*>(&Ct[((long)b * T_ + n0 + n) * O_ + m0 + mq * 16]) = zh;
        }
        return;
    }

    const __half* Wb = Wh + (long)m0 * D_;
    const __half* Xb = Xt + ((long)b * T_ + n0) * D_;

    #pragma unroll
    for (int e = 0; e < 8; e++) {
        int idx = tid + e * 256;
        int ch = idx >> 8;
        int row = (idx & 255) >> 2;
        int cb = (idx & 3) * 16;
        cpasync16(sb + ch * 4096 + paddr(row, cb),
                  Wb + (long)row * D_ + ch * 32 + cb / 2);
    }
    CP_COMMIT();

    auto load_b = [&](int ch, int st) {
        #pragma unroll
        for (int e = 0; e < 2; e++) {
            int idx = tid + e * 256;
            int row = idx >> 2;
            int cb = (idx & 3) * 16;
            cpasync16(sb + 32768 + st * 8192 + paddr(row, cb),
                      Xb + (long)row * D_ + ch * 32 + cb / 2);
        }
    };
    load_b(0, 0);
    CP_COMMIT();

    float acc[32];
    #pragma unroll
    for (int i = 0; i < 32; i++) acc[i] = 0.f;

    for (int ch = 0; ch < 8; ch++) {
        int st = ch & 1;
        if (ch + 1 < 8) {
            load_b(ch + 1, st ^ 1);
            CP_COMMIT();
            CP_WAIT(1);
        } else {
            CP_WAIT(0);
        }
        __syncthreads();
        uint32_t abase = sb + ch * 4096;
        uint32_t bbase = sb + 32768 + st * 8192;
        #pragma unroll
        for (int os = 0; os < 2; os++) {
            uint32_t colb = (uint32_t)(os * 32 + lh * 16);
            uint32_t arow = (uint32_t)(wi * 32 + l16);
            uint32_t brow = (uint32_t)(wj * 32 + l16);
            uint32_t a0[4], a1[4], b0r[4], b1r[4];
            ldsm4(a0, abase + paddr(arow, colb));
            ldsm4(a1, abase + paddr(arow + 16, colb));
            ldsm4(b0r, bbase + paddr(brow, colb));
            ldsm4(b1r, bbase + paddr(brow + 16, colb));
            #pragma unroll
            for (int mt = 0; mt < 2; mt++) {
                const uint32_t* a = mt ? a1 : a0;
                #pragma unroll
                for (int nt = 0; nt < 4; nt++) {
                    const uint32_t* bb = (nt >> 1) ? b1r : b0r;
                    int s = nt & 1;
                    mma16816h(acc + (mt * 4 + nt) * 4, a, bb[s], bb[s + 2]);
                }
            }
        }
        __syncthreads();
    }

    __half* Cs = reinterpret_cast<__half*>(gsm);
    int r4 = lane >> 2, c2 = (lane & 3) * 2;
    #pragma unroll
    for (int mt = 0; mt < 2; mt++) {
        #pragma unroll
        for (int nt = 0; nt < 4; nt++) {
            float* d = acc + (mt * 4 + nt) * 4;
            #pragma unroll
            for (int half_ = 0; half_ < 2; half_++) {
                int row = wi * 32 + mt * 16 + r4 + half_ * 8;
                int col = wj * 32 + nt * 8 + c2;
                int m = m0 + row, n = n0 + col;
                float bi = bias[m];
                float v0 = fmaxf(d[half_ * 2 + 0] - NEGC * pad[b * T_ + n] + bi, 0.f);
                float v1 = fmaxf(d[half_ * 2 + 1] - NEGC * pad[b * T_ + n + 1] + bi, 0.f);
                float* dst = &C[((long)b * O_ + m) * T_ + n];
                dst[0] = v0; dst[1] = v1;
                Cs[row * 136 + col] = __float2half(v0);
                Cs[row * 136 + col + 1] = __float2half(v1);
            }
        }
    }
    __syncthreads();
    {
        int n = tid >> 1;
        int mh = (tid & 1) * 32;
        __half hbuf[32];
        #pragma unroll
        for (int mm = 0; mm < 32; mm++) hbuf[mm] = Cs[(mh + mm) * 136 + n];
        uint4* dst = reinterpret_cast<uint4*>(&Ct[((long)b * T_ + n0 + n) * O_ + m0 + mh]);
        const uint4* srcv = reinterpret_cast<const uint4*>(hbuf);
        dst[0] = srcv[0]; dst[1] = srcv[1]; dst[2] = srcv[2]; dst[3] = srcv[3];
    }
}

// ---------------- fp16 HMMA W2 GEMM (merged via blockIdx.z) ----------------
__global__ __launch_bounds__(256) void wgemm_h_kernel(
    const __half* __restrict__ W2Rh, const __half* __restrict__ W2Qh,
    const __half* __restrict__ Rt, const __half* __restrict__ Qt,
    __half* __restrict__ OutR, __half* __restrict__ OutQ) {
    __shared__ char gsm[49152];
    uint32_t sb = smem_to_u32(gsm);
    int z = blockIdx.z;
    int sel = z >> 5, b = z & 31;
    const __half* W2h = sel ? W2Qh : W2Rh;
    const __half* Xt = sel ? Qt : Rt;
    __half* Out = sel ? OutQ : OutR;

    int n0 = blockIdx.x * 128;
    int tid = threadIdx.x, lane = tid & 31, w = tid >> 5;
    int wi = w >> 2, wj = w & 3;
    int l16 = lane & 15, lh = lane >> 4;
    const __half* Xb = Xt + ((long)b * T_ + n0) * O_;

    #pragma unroll
    for (int e = 0; e < 8; e++) {
        int idx = tid + e * 256;
        int ch = idx >> 8;
        int row = (idx & 255) >> 2;
        int cb = (idx & 3) * 16;
        cpasync16(sb + ch * 4096 + paddr(row, cb),
                  W2h + (long)row * O_ + ch * 32 + cb / 2);
    }
    CP_COMMIT();

    auto load_b = [&](int ch, int st) {
        #pragma unroll
        for (int e = 0; e < 2; e++) {
            int idx = tid + e * 256;
            int row = idx >> 2;
            int cb = (idx & 3) * 16;
            cpasync16(sb + 32768 + st * 8192 + paddr(row, cb),
                      Xb + (long)row * O_ + ch * 32 + cb / 2);
        }
    };
    load_b(0, 0);
    CP_COMMIT();

    float acc[32];
    #pragma unroll
    for (int i = 0; i < 32; i++) acc[i] = 0.f;

    for (int ch = 0; ch < 8; ch++) {
        int st = ch & 1;
        if (ch + 1 < 8) {
            load_b(ch + 1, st ^ 1);
            CP_COMMIT();
            CP_WAIT(1);
        } else {
            CP_WAIT(0);
        }
        __syncthreads();
        uint32_t abase = sb + ch * 4096;
        uint32_t bbase = sb + 32768 + st * 8192;
        #pragma unroll
        for (int os = 0; os < 2; os++) {
            uint32_t colb = (uint32_t)(os * 32 + lh * 16);
            uint32_t arow = (uint32_t)(wi * 32 + l16);
            uint32_t brow = (uint32_t)(wj * 32 + l16);
            uint32_t a0[4], a1[4], b0r[4], b1r[4];
            ldsm4(a0, abase + paddr(arow, colb));
            ldsm4(a1, abase + paddr(arow + 16, colb));
            ldsm4(b0r, bbase + paddr(brow, colb));
            ldsm4(b1r, bbase + paddr(brow + 16, colb));
            #pragma unroll
            for (int mt = 0; mt < 2; mt++) {
                const uint32_t* a = mt ? a1 : a0;
                #pragma unroll
                for (int nt = 0; nt < 4; nt++) {
                    const uint32_t* bb = (nt >> 1) ? b1r : b0r;
                    int s = nt & 1;
                    mma16816h(acc + (mt * 4 + nt) * 4, a, bb[s], bb[s + 2]);
                }
            }
        }
        __syncthreads();
    }

    int r4 = lane >> 2, c2 = (lane & 3) * 2;
    #pragma unroll
    for (int mt = 0; mt < 2; mt++) {
        #pragma unroll
        for (int nt = 0; nt < 4; nt++) {
            float* d = acc + (mt * 4 + nt) * 4;
            #pragma unroll
            for (int half_ = 0; half_ < 2; half_++) {
                int g = wi * 32 + mt * 16 + r4 + half_ * 8;
                int t = n0 + wj * 32 + nt * 8 + c2;
                __half2 v = __floats2half2_rn(d[half_ * 2], d[half_ * 2 + 1]);
                *reinterpret_cast<__half2*>(&Out[((long)b * G_ + g) * T_ + t]) = v;
            }
        }
    }
}

// ======================= fp16 HMMA F kernel (R13 shape: 128i x 64j, 256 thr) =======================
#define FS_B 32768
#define FS_TOTAL 98304

__global__ __launch_bounds__(256, 2) void f_mma_kernel(
    const __half* __restrict__ Uk, const __half* __restrict__ Vk,
    const __half* __restrict__ Rt, const __half* __restrict__ Qt,
    __half* __restrict__ Ft, const int* __restrict__ jmin, const int* __restrict__ imax) {
    extern __shared__ char sm[];
    uint32_t sb = smem_to_u32(sm);
    int tid = threadIdx.x, lane = tid & 31, w = tid >> 5;
    int wi = w >> 1, wj = w & 1;
    int b = blockIdx.z, i0 = blockIdx.y * 128, j0 = blockIdx.x * 64;
    int l16 = lane & 15, lh = lane >> 4;

    if (i0 >= imax[b]) return;

    if (j0 >= jmin[b]) {
        int j = tid >> 2, iq = (tid & 3) * 32;
        uint4 z4 = make_uint4(0, 0, 0, 0);
        uint4* dst = reinterpret_cast<uint4*>(&Ft[((long)b * T_ + j0 + j) * T_ + i0 + iq]);
        dst[0] = z4; dst[1] = z4; dst[2] = z4; dst[3] = z4;
        return;
    }

    const __half* apt[2] = {Uk, Vk};
    const __half* bpt[2] = {Rt, Qt};

    #pragma unroll
    for (int arr = 0; arr < 2; arr++) {
        const __half* src = bpt[arr] + ((long)b * T_ + j0) * O_;
        #pragma unroll
        for (int e = 0; e < 8; e++) {
            int idx = tid + e * 256;
            int ch = idx >> 8;
            int row = (idx & 255) >> 2;
            int cb = (idx & 3) * 16;
            const void* g = src + (long)row * O_ + ch * 32 + cb / 2;
            cpasync16(sb + FS_B + arr * 32768 + ch * 4096 + paddr(row, cb), g);
        }
    }
    CP_COMMIT();

    auto load_a = [&](int cu, int st) {
        int k = cu >> 3, ch = cu & 7;
        #pragma unroll
        for (int arr = 0; arr < 2; arr++) {
            const __half* src = apt[arr] + ((long)k * T_ + i0) * O_ + ch * 32;
            #pragma unroll
            for (int e = 0; e < 2; e++) {
                int idx = tid + e * 256;
                int row = idx >> 2;
                int cb = (idx & 3) * 16;
                const void* g = src + (long)row * O_ + cb / 2;
                cpasync16(sb + st * 16384 + arr * 8192 + paddr(row, cb), g);
            }
        }
    };

    load_a(0, 0);
    CP_COMMIT();

    float f[32], d1[32], d2[32];
    #pragma unroll
    for (int i = 0; i < 32; i++) { f[i] = 0.f; d1[i] = 0.f; d2[i] = 0.f; }

    for (int cu = 0; cu < 64; cu++) {
        int st = cu & 1, ch = cu & 7;
        if (cu + 1 < 64) {
            load_a(cu + 1, (cu + 1) & 1);
            CP_COMMIT();
            CP_WAIT(1);
        } else {
            CP_WAIT(0);
        }
        __syncthreads();

        uint32_t abase = sb + st * 16384;
        #pragma unroll
        for (int os = 0; os < 2; os++) {
            uint32_t colb = (uint32_t)(os * 32 + lh * 16);
            uint32_t arow = (uint32_t)(wi * 32 + l16);
            uint32_t brow = (uint32_t)(wj * 32 + l16);
            {
                uint32_t a0[4], a1[4], b0r[4], b1r[4];
                ldsm4(a0, abase + 0 * 8192 + paddr(arow, colb));
                ldsm4(a1, abase + 0 * 8192 + paddr(arow + 16, colb));
                uint32_t bb0 = sb + FS_B + 0 * 32768 + ch * 4096;
                ldsm4(b0r, bb0 + paddr(brow, colb));
                ldsm4(b1r, bb0 + paddr(brow + 16, colb));
                #pragma unroll
                for (int mt = 0; mt < 2; mt++) {
                    const uint32_t* a = mt ? a1 : a0;
                    #pragma unroll
                    for (int nt = 0; nt < 4; nt++) {
                        const uint32_t* bb = (nt >> 1) ? b1r : b0r;
                        int s = nt & 1;
                        mma16816h(d1 + (mt * 4 + nt) * 4, a, bb[s], bb[s + 2]);
                    }
                }
            }
            {
                uint32_t a0[4], a1[4], b0r[4], b1r[4];
                ldsm4(a0, abase + 1 * 8192 + paddr(arow, colb));
                ldsm4(a1, abase + 1 * 8192 + paddr(arow + 16, colb));
                uint32_t bb1 = sb + FS_B + 1 * 32768 + ch * 4096;
                ldsm4(b0r, bb1 + paddr(brow, colb));
                ldsm4(b1r, bb1 + paddr(brow + 16, colb));
                #pragma unroll
                for (int mt = 0; mt < 2; mt++) {
                    const uint32_t* a = mt ? a1 : a0;
                    #pragma unroll
                    for (int nt = 0; nt < 4; nt++) {
                        const uint32_t* bb = (nt >> 1) ? b1r : b0r;
                        int s = nt & 1;
                        mma16816h(d2 + (mt * 4 + nt) * 4, a, bb[s], bb[s + 2]);
                    }
                }
            }
        }
        if (ch == 7) {
            #pragma unroll
            for (int i = 0; i < 32; i++) {
                f[i] += d1[i] * d2[i];
                d1[i] = 0.f; d2[i] = 0.f;
            }
        }
        __syncthreads();
    }

    // stage fp16 tile [128 i][72 j] into A-ring SMEM, then coalesced transposed write
    __half* Fs16 = reinterpret_cast<__half*>(sm);
    int r4 = lane >> 2, c2 = (lane & 3) * 2;
    #pragma unroll
    for (int mt = 0; mt < 2; mt++) {
        #pragma unroll
        for (int nt = 0; nt < 4; nt++) {
            float* d = f + (mt * 4 + nt) * 4;
            #pragma unroll
            for (int hh = 0; hh < 2; hh++) {
                int i_l = wi * 32 + mt * 16 + r4 + hh * 8;
                int j_l = wj * 32 + nt * 8 + c2;
                *reinterpret_cast<__half2*>(&Fs16[i_l * 72 + j_l]) =
                    __floats2half2_rn(d[hh * 2], d[hh * 2 + 1]);
            }
        }
    }
    __syncthreads();
    {
        int j = tid >> 2, iq = (tid & 3) * 32;
        __half hbuf[32];
        #pragma unroll
        for (int ii = 0; ii < 32; ii++) hbuf[ii] = Fs16[(iq + ii) * 72 + j];
        uint4* dst = reinterpret_cast<uint4*>(&Ft[((long)b * T_ + j0 + j) * T_ + i0 + iq]);
        const uint4* s4 = reinterpret_cast<const uint4*>(hbuf);
        dst[0] = s4[0]; dst[1] = s4[1]; dst[2] = s4[2]; dst[3] = s4[3];
    }
}

// ---------------- fp16 HMMA fused M + d kernel (merged via blockIdx.z) ----------------
__global__ __launch_bounds__(128) void md_h_kernel(
    const __half* __restrict__ WRb, const __half* __restrict__ WQb,
    const __half* __restrict__ Ft,
    const float* __restrict__ wmv, const float* __restrict__ wmq,
    const float* __restrict__ pq, const float* __restrict__ pv,
    float* __restrict__ d1, float* __restrict__ d2,
    const int* __restrict__ l1, const int* __restrict__ l2) {
    __shared__ char msm[16384];
    __shared__ float red[64][65];
    __shared__ float p2[2][64];
    uint32_t sb = smem_to_u32(msm);
    int sel = blockIdx.z;
    int b = blockIdx.y, c0 = blockIdx.x * 64;
    const __half* Bias = sel ? WQb : WRb;
    const __half* Mul  = sel ? WRb : WQb;
    const float* wv = sel ? wmq : wmv;
    const float* pad = sel ? pv : pq;
    float* d = sel ? d2 : d1;
    const int* lencol = sel ? l2 : l1;
    const int* lenmul = sel ? l1 : l2;

    int tid = threadIdx.x, lane = tid & 31, w_ = tid >> 5;
    int wg = w_ >> 1, wc = w_ & 1;
    int l16 = lane & 15, lh = lane >> 4;

    if (c0 >= lencol[b]) {
        if (tid < 64) d[b * T_ + c0 + tid] = -NEGC;
        return;
    }
    int nch = ((lenmul[b] + 31) & ~31) >> 5;
    const __half* Mb = Mul + (long)b * G_ * T_;
    const __half* Fb = Ft + ((long)b * T_ + c0) * T_;

    auto load_ch = [&](int ch, int st) {
        #pragma unroll
        for (int e = 0; e < 2; e++) {
            int idx = tid + e * 128;
            int row = idx >> 2, cb = (idx & 3) * 16;
            cpasync16(sb + st * 8192 + paddr(row, cb), Mb + (long)row * T_ + ch * 32 + cb / 2);
        }
        #pragma unroll
        for (int e = 0; e < 2; e++) {
            int idx = tid + e * 128;
            int row = idx >> 2, cb = (idx & 3) * 16;
            cpasync16(sb + st * 8192 + 4096 + paddr(row, cb), Fb + (long)row * T_ + ch * 32 + cb / 2);
        }
    };
    load_ch(0, 0);
    CP_COMMIT();

    float acc[32];
    #pragma unroll
    for (int i = 0; i < 32; i++) acc[i] = 0.f;

    for (int ch = 0; ch < nch; ch++) {
        int st = ch & 1;
        if (ch + 1 < nch) {
            load_ch(ch + 1, st ^ 1);
            CP_COMMIT();
            CP_WAIT(1);
        } else {
            CP_WAIT(0);
        }
        __syncthreads();
        uint32_t ab = sb + st * 8192, bb_ = ab + 4096;
        #pragma unroll
        for (int os = 0; os < 2; os++) {
            uint32_t colb = (uint32_t)(os * 32 + lh * 16);
            uint32_t arow = (uint32_t)(wg * 32 + l16);
            uint32_t brow = (uint32_t)(wc * 32 + l16);
            uint32_t a0[4], a1[4], b0r[4], b1r[4];
            ldsm4(a0, ab + paddr(arow, colb));
            ldsm4(a1, ab + paddr(arow + 16, colb));
            ldsm4(b0r, bb_ + paddr(brow, colb));
            ldsm4(b1r, bb_ + paddr(brow + 16, colb));
            #pragma unroll
            for (int mt = 0; mt < 2; mt++) {
                const uint32_t* a = mt ? a1 : a0;
                #pragma unroll
                for (int nt = 0; nt < 4; nt++) {
                    const uint32_t* bb = (nt >> 1) ? b1r : b0r;
                    int s = nt & 1;
                    mma16816h(acc + (mt * 4 + nt) * 4, a, bb[s], bb[s + 2]);
                }
            }
        }
        __syncthreads();
    }

    int r4 = lane >> 2, c2 = (lane & 3) * 2;
    #pragma unroll
    for (int mt = 0; mt < 2; mt++) {
        #pragma unroll
        for (int nt = 0; nt < 4; nt++) {
            float* dd = acc + (mt * 4 + nt) * 4;
            #pragma unroll
            for (int hh = 0; hh < 2; hh++) {
                int g = wg * 32 + mt * 16 + r4 + hh * 8;
                int col = wc * 32 + nt * 8 + c2;
                float wgt = wv[g];
                float bi0 = __half2float(Bias[(long)b * G_ * T_ + g * T_ + c0 + col]);
                float bi1 = __half2float(Bias[(long)b * G_ * T_ + g * T_ + c0 + col + 1]);
                red[g][col]     = wgt * fmaxf(dd[hh * 2 + 0] + bi0, 0.f);
                red[g][col + 1] = wgt * fmaxf(dd[hh * 2 + 1] + bi1, 0.f);
            }
        }
    }
    __syncthreads();
    {
        int col = tid & 63, h = tid >> 6;
        float s = 0.f;
        #pragma unroll
        for (int g = 0; g < 32; g++) s += red[h * 32 + g][col];
        p2[h][col] = s;
    }
    __syncthreads();
    if (tid < 64)
        d[b * T_ + c0 + tid] = p2[0][tid] + p2[1][tid] - NEGC * pad[b * T_ + c0 + tid];
}

// ---------------- softmax ----------------
__global__ void softmax_kernel(const float* __restrict__ d1, const float* __restrict__ d2,
                               float* __restrict__ g1, float* __restrict__ g2) {
    int b = blockIdx.x;
    const float* d = blockIdx.y ? d2 : d1;
    float* g = blockIdx.y ? g2 : g1;
    int t = threadIdx.x;
    float v = d[b * T_ + t];
    __shared__ float red[16];
    float m = v;
    #pragma unroll
    for (int o = 16; o; o >>= 1) m = fmaxf(m, __shfl_xor_sync(0xffffffffu, m, o));
    if ((t & 31) == 0) red[t >> 5] = m;
    __syncthreads();
    if (t < 32) {
        float x = (t < 16) ? red[t] : -3.4e38f;
        #pragma unroll
        for (int o = 8; o; o >>= 1) x = fmaxf(x, __shfl_xor_sync(0xffffffffu, x, o));
        if (t == 0) red[0] = x;
    }
    __syncthreads();
    float mx = red[0];
    __syncthreads();
    float e = expf(v - mx);
    float s = e;
    #pragma unroll
    for (int o = 16; o; o >>= 1) s += __shfl_xor_sync(0xffffffffu, s, o);
    if ((t & 31) == 0) red[t >> 5] = s;
    __syncthreads();
    if (t < 32) {
        float x = (t < 16) ? red[t] : 0.f;
        #pragma unroll
        for (int o = 8; o; o >>= 1) x += __shfl_xor_sync(0xffffffffu, x, o);
        if (t == 0) red[0] = x;
    }
    __syncthreads();
    g[b * T_ + t] = e / red[0];
}

// ---------------- final reduction ----------------
__global__ void final_kernel(const float* __restrict__ R, const float* __restrict__ Q,
                             const float* __restrict__ gv, const float* __restrict__ gq,
                             float* __restrict__ out) {
    int b = blockIdx.x;
    __shared__ float sgv[T_], sgq[T_];
    int tid = threadIdx.x;
    sgv[tid] = gv[b * T_ + tid];
    sgq[tid] = gq[b * T_ + tid];
    __syncthreads();
    int o = tid & 255;
    int h = tid >> 8;
    const float* Rb = R + (long)b * O_ * T_;
    const float* Qb = Q + (long)b * O_ * T_;
    float tr = 0.f, lg = 0.f;
    #pragma unroll 4
    for (int t = h * 256; t < h * 256 + 256; t++) {
        tr += sgv[t] * Rb[t * O_ + o];
        lg += sgq[t] * Qb[t * O_ + o];
    }
    __shared__ float str[2][256], slg[2][256];
    str[h][o] = tr;
    slg[h][o] = lg;
    __syncthreads();
    if (h == 0) out[b * O_ + o] = (str[0][o] + str[1][o]) * (slg[0][o] + slg[1][o]);
}

// ---------------- launcher ----------------
extern "C" void kernel_launch(void* const* d_in, const int* in_sizes, int n_in,
                              void* d_out, int out_size) {
    const float* x0  = (const float*)d_in[0];
    const float* x1  = (const float*)d_in[1];
    const unsigned char* qm = (const unsigned char*)d_in[2];
    const unsigned char* vm = (const unsigned char*)d_in[3];
    const float* W_R = (const float*)d_in[4];
    const float* W_Q = (const float*)d_in[5];
    const float* br  = (const float*)d_in[6];
    const float* bq  = (const float*)d_in[7];
    const float* U   = (const float*)d_in[8];
    const float* V   = (const float*)d_in[9];
    const float* W2R = (const float*)d_in[10];
    const float* W2Q = (const float*)d_in[11];
    const float* wmv = (const float*)d_in[12];
    const float* wmq = (const float*)d_in[13];
    float* out = (float*)d_out;

    float *pR, *pQ, *pd1, *pd2, *pg1, *pg2, *ppq, *ppv;
    int *pl1, *pl2, *pjm, *pim;
    __half *pUk, *pVk, *pRt, *pQt, *pWRh, *pWQh, *pW2Rh, *pW2Qh, *px0t, *px1t, *pFt, *pWRb, *pWQb;
    cudaGetSymbolAddress((void**)&pR,  g_R);
    cudaGetSymbolAddress((void**)&pQ,  g_Q);
    cudaGetSymbolAddress((void**)&pd1, g_d1);
    cudaGetSymbolAddress((void**)&pd2, g_d2);
    cudaGetSymbolAddress((void**)&pg1, g_g1);
    cudaGetSymbolAddress((void**)&pg2, g_g2);
    cudaGetSymbolAddress((void**)&ppq, g_pq);
    cudaGetSymbolAddress((void**)&ppv, g_pv);
    cudaGetSymbolAddress((void**)&pl1, g_len1);
    cudaGetSymbolAddress((void**)&pl2, g_len2);
    cudaGetSymbolAddress((void**)&pjm, g_jmin);
    cudaGetSymbolAddress((void**)&pim, g_imax);
    cudaGetSymbolAddress((void**)&pUk, g_Uk);
    cudaGetSymbolAddress((void**)&pVk, g_Vk);
    cudaGetSymbolAddress((void**)&pRt, g_Rt);
    cudaGetSymbolAddress((void**)&pQt, g_Qt);
    cudaGetSymbolAddress((void**)&pWRh, g_WRh);
    cudaGetSymbolAddress((void**)&pWQh, g_WQh);
    cudaGetSymbolAddress((void**)&pW2Rh, g_W2Rh);
    cudaGetSymbolAddress((void**)&pW2Qh, g_W2Qh);
    cudaGetSymbolAddress((void**)&px0t, g_x0t);
    cudaGetSymbolAddress((void**)&px1t, g_x1t);
    cudaGetSymbolAddress((void**)&pFt, g_Ft);
    cudaGetSymbolAddress((void**)&pWRb, g_WRb);
    cudaGetSymbolAddress((void**)&pWQb, g_WQb);

    static bool attr_done = false;
    if (!attr_done) {
        cudaFuncSetAttribute(f_mma_kernel, cudaFuncAttributeMaxDynamicSharedMemorySize, FS_TOTAL);
        attr_done = true;
    }

    lens_kernel<<<B_, T_>>>(qm, vm, ppq, ppv, pl1, pl2, pjm, pim);
    convs_kernel<<<(KF_ * T_ * O_ + 255) / 256, 256>>>(
        U, V, W_R, W_Q, W2R, W2Q, pUk, pVk, pWRh, pWQh, pW2Rh, pW2Qh);
    convX_kernel<<<dim3(T_ / 32, D_ / 32, 2 * B_), dim3(32, 8)>>>(x0, x1, px0t, px1t);

    gemm_rq_h_kernel<<<dim3(T_ / 128, O_ / 64, 2 * B_), 256>>>(
        pWRh, pWQh, px0t, px1t, pR, pQ, pRt, pQt, br, bq, ppq, ppv, pl1, pl2);

    f_mma_kernel<<<dim3(T_ / 64, T_ / 128, B_), 256, FS_TOTAL>>>(
        pUk, pVk, pRt, pQt, pFt, pjm, pim);

    wgemm_h_kernel<<<dim3(T_ / 128, 1, 2 * B_), 256>>>(
        pW2Rh, pW2Qh, pRt, pQt, pWRb, pWQb);

    md_h_kernel<<<dim3(T_ / 64, B_, 2), 128>>>(
        pWRb, pWQb, pFt, wmv, wmq, ppq, ppv, pd1, pd2, pl1, pl2);

    softmax_kernel<<<dim3(B_, 2), T_>>>(pd1, pd2, pg1, pg2);

    final_kernel<<<B_, T_>>>(pR, pQ, pg1, pg2, out);
}

// round 16
// speedup vs baseline: 1.1575x; 1.0333x over previous
#include <cuda_runtime.h>
#include <cuda_fp16.h>
#include <cstdint>

#define NEGC 1e9f

#define B_  32
#define T_  512
#define D_  256
#define O_  256
#define KF_ 8
#define G_  64

// ---------------- scratch ----------------
__device__ float g_R [B_ * O_ * T_];
__device__ float g_Q [B_ * O_ * T_];
__device__ float g_d1[B_ * T_];
__device__ float g_d2[B_ * T_];
__device__ float g_g1[B_ * T_];
__device__ float g_g2[B_ * T_];
__device__ float g_pq[B_ * T_];
__device__ float g_pv[B_ * T_];
__device__ int   g_len1[B_];
__device__ int   g_len2[B_];
__device__ int   g_jmin[B_];
__device__ int   g_imax[B_];

__device__ __half g_Uk[KF_ * T_ * O_];
__device__ __half g_Vk[KF_ * T_ * O_];
__device__ __half g_Rt[B_ * T_ * O_];
__device__ __half g_Qt[B_ * T_ * O_];
__device__ __half g_WRh[O_ * D_];
__device__ __half g_WQh[O_ * D_];
__device__ __half g_W2Rh[G_ * O_];
__device__ __half g_W2Qh[G_ * O_];
__device__ __half g_x0t[B_ * T_ * D_];
__device__ __half g_x1t[B_ * T_ * D_];
__device__ __half g_Ft [B_ * T_ * T_];
__device__ __half g_WRb[B_ * G_ * T_];
__device__ __half g_WQb[B_ * G_ * T_];

// =================== helpers ===================
__device__ __forceinline__ uint32_t smem_to_u32(const void* p) {
    uint32_t a;
    asm("{ .reg .u64 t; cvta.to.shared.u64 t, %1; cvt.u32.u64 %0, t; }" : "=r"(a) : "l"(p));
    return a;
}
__device__ __forceinline__ void ldsm4(uint32_t* r, uint32_t addr) {
    asm volatile("ldmatrix.sync.aligned.m8n8.x4.shared.b16 {%0,%1,%2,%3}, [%4];"
        : "=r"(r[0]), "=r"(r[1]), "=r"(r[2]), "=r"(r[3]) : "r"(addr));
}
__device__ __forceinline__ void mma16816h(float* d, const uint32_t* a,
                                          uint32_t b0, uint32_t b1) {
    asm volatile("mma.sync.aligned.m16n8k16.row.col.f32.f16.f16.f32 "
        "{%0,%1,%2,%3}, {%4,%5,%6,%7}, {%8,%9}, {%0,%1,%2,%3};"
        : "+f"(d[0]), "+f"(d[1]), "+f"(d[2]), "+f"(d[3])
        : "r"(a[0]), "r"(a[1]), "r"(a[2]), "r"(a[3]), "r"(b0), "r"(b1));
}
__device__ __forceinline__ void cpasync16(uint32_t dst, const void* src) {
    asm volatile("cp.async.cg.shared.global [%0], [%1], 16;" :: "r"(dst), "l"(src));
}
#define CP_COMMIT() asm volatile("cp.async.commit_group;" ::: "memory")
#define CP_WAIT(n)  asm volatile("cp.async.wait_group %0;" :: "n"(n) : "memory")

__device__ __forceinline__ uint32_t paddr(uint32_t row, uint32_t cb) {
    uint32_t pr = row >> 1;
    return pr * 128 + ((((row & 1) << 6) + cb) ^ ((pr & 7) << 4));
}

__device__ __forceinline__ void decode_mask(const unsigned char* q, const unsigned char* v,
                                            int i, bool& qv, bool& vv) {
    unsigned char b1 = q[1], b3 = q[3];
    int type = (b1 == 1) ? 0 : (b1 == 0x3F) ? 3 : (b3 == 0x3F) ? 2 : 1;
    switch (type) {
        case 0: qv = q[i] != 0;                            vv = v[i] != 0; break;
        case 1: qv = ((const int*)q)[i] != 0;              vv = ((const int*)v)[i] != 0; break;
        case 2: qv = ((const float*)q)[i] != 0.f;          vv = ((const float*)v)[i] != 0.f; break;
        default: qv = ((const unsigned short*)q)[i] != 0;  vv = ((const unsigned short*)v)[i] != 0; break;
    }
}

// ---------------- lens + mask decode (fused) ----------------
__global__ void lens_kernel(const unsigned char* __restrict__ q,
                            const unsigned char* __restrict__ v,
                            float* __restrict__ pq, float* __restrict__ pv,
                            int* __restrict__ len1, int* __restrict__ len2,
                            int* __restrict__ jmin, int* __restrict__ imax) {
    __shared__ int s1, s2;
    int b = blockIdx.x, t = threadIdx.x;
    if (t == 0) { s1 = 0; s2 = 0; }
    __syncthreads();
    bool qv, vv;
    decode_mask(q, v, b * T_ + t, qv, vv);
    pq[b * T_ + t] = qv ? 0.f : 1.f;
    pv[b * T_ + t] = vv ? 0.f : 1.f;
    unsigned m1 = __ballot_sync(0xffffffffu, qv);
    unsigned m2 = __ballot_sync(0xffffffffu, vv);
    if ((t & 31) == 0) { atomicAdd(&s1, __popc(m1)); atomicAdd(&s2, __popc(m2)); }
    __syncthreads();
    if (t == 0) {
        len1[b] = s1; len2[b] = s2;
        jmin[b] = s1 < s2 ? s1 : s2;
        imax[b] = s1 > s2 ? s1 : s2;
    }
}

// ---------------- U/V de-interleave + W/W2 conversion (fused) ----------------
__global__ void convs_kernel(const float* __restrict__ U, const float* __restrict__ V,
                             const float* __restrict__ WR, const float* __restrict__ WQ,
                             const float* __restrict__ W2R, const float* __restrict__ W2Q,
                             __half* __restrict__ Uo, __half* __restrict__ Vo,
                             __half* __restrict__ WRh, __half* __restrict__ WQh,
                             __half* __restrict__ W2Rh, __half* __restrict__ W2Qh) {
    int idx = blockIdx.x * blockDim.x + threadIdx.x;
    if (idx < KF_ * T_ * O_) {
        int k = idx >> 17;
        int m = idx & (T_ * O_ - 1);
        Uo[idx] = __float2half(U[m * KF_ + k]);
        Vo[idx] = __float2half(V[m * KF_ + k]);
    }
    if (idx < O_ * D_) {
        WRh[idx] = __float2half(WR[idx]);
        WQh[idx] = __float2half(WQ[idx]);
    }
    if (idx < G_ * O_) {
        W2Rh[idx] = __float2half(W2R[idx]);
        W2Qh[idx] = __float2half(W2Q[idx]);
    }
}

// ---------------- x transpose -> fp16 ----------------
__global__ void convX_kernel(const float* __restrict__ x0, const float* __restrict__ x1,
                             __half* __restrict__ x0t, __half* __restrict__ x1t) {
    __shared__ float tile[32][33];
    int zz = blockIdx.z;
    int b = zz & 31;
    bool is1 = (zz >> 5) != 0;
    const float* src = (is1 ? x1 : x0) + (long)b * D_ * T_;
    __half* dst = (is1 ? x1t : x0t) + (long)b * T_ * D_;
    int t0 = blockIdx.x * 32, k0 = blockIdx.y * 32;
    int tx = threadIdx.x, ty = threadIdx.y;
    #pragma unroll
    for (int r = 0; r < 4; r++)
        tile[ty + r * 8][tx] = src[(long)(k0 + ty + r * 8) * T_ + t0 + tx];
    __syncthreads();
    #pragma unroll
    for (int r = 0; r < 4; r++)
        dst[(long)(t0 + ty + r * 8) * D_ + k0 + tx] = __float2half(tile[tx][ty + r * 8]);
}

// ---------------- fp16 HMMA R/Q GEMM (merged; dynamic smem for occupancy) ----------------
__global__ __launch_bounds__(256) void gemm_rq_h_kernel(
    const __half* __restrict__ WRh, const __half* __restrict__ WQh,
    const __half* __restrict__ X0t, const __half* __restrict__ X1t,
    float* __restrict__ CR, float* __restrict__ CQ,
    __half* __restrict__ CRt, __half* __restrict__ CQt,
    const float* __restrict__ br, const float* __restrict__ bq,
    const float* __restrict__ pq, const float* __restrict__ pv,
    const int* __restrict__ l1, const int* __restrict__ l2) {
    extern __shared__ char gsm[];
    uint32_t sb = smem_to_u32(gsm);
    int z = blockIdx.z;
    int sel = z >> 5, b = z & 31;
    const __half* Wh = sel ? WQh : WRh;
    const __half* Xt = sel ? X1t : X0t;
    float* C = sel ? CQ : CR;
    __half* Ct = sel ? CQt : CRt;
    const float* bias = sel ? bq : br;
    const float* pad = sel ? pv : pq;
    const int* lenp = sel ? l2 : l1;

    int n0 = blockIdx.x * 128;
    int m0 = blockIdx.y * 64;
    int tid = threadIdx.x, lane = tid & 31, w = tid >> 5;
    int wi = w >> 2, wj = w & 3;
    int l16 = lane & 15, lh = lane >> 4;

    if (n0 >= lenp[b]) {
        float4 zf = make_float4(0.f, 0.f, 0.f, 0.f);
        #pragma unroll
        for (int e = 0; e < 8; e++) {
            int idx = tid + e * 256;
            int m = idx >> 5, nq = idx & 31;
            *reinterpret_cast<float4*>(&C[((long)b * O_ + m0 + m) * T_ + n0 + nq * 4]) = zf;
        }
        uint4 zh = make_uint4(0, 0, 0, 0);
        #pragma unroll
        for (int e = 0; e < 2; e++) {
            int idx = tid + e * 256;
            int n = idx >> 2, mq = idx & 3;
            *reinterpret_cast<uint4*>(&Ct[((long)b * T_ + n0 + n) * O_ + m0 + mq * 16]) = zh;
        }
        return;
    }

    const __half* Wb = Wh + (long)m0 * D_;
    const __half* Xb = Xt + ((long)b * T_ + n0) * D_;

    #pragma unroll
    for (int e = 0; e < 8; e++) {
        int idx = tid + e * 256;
        int ch = idx >> 8;
        int row = (idx & 255) >> 2;
        int cb = (idx & 3) * 16;
        cpasync16(sb + ch * 4096 + paddr(row, cb),
                  Wb + (long)row * D_ + ch * 32 + cb / 2);
    }
    CP_COMMIT();

    auto load_b = [&](int ch, int st) {
        #pragma unroll
        for (int e = 0; e < 2; e++) {
            int idx = tid + e * 256;
            int row = idx >> 2;
            int cb = (idx & 3) * 16;
            cpasync16(sb + 32768 + st * 8192 + paddr(row, cb),
                      Xb + (long)row * D_ + ch * 32 + cb / 2);
        }
    };
    load_b(0, 0);
    CP_COMMIT();

    float acc[32];
    #pragma unroll
    for (int i = 0; i < 32; i++) acc[i] = 0.f;

    for (int ch = 0; ch < 8; ch++) {
        int st = ch & 1;
        if (ch + 1 < 8) {
            load_b(ch + 1, st ^ 1);
            CP_COMMIT();
            CP_WAIT(1);
        } else {
            CP_WAIT(0);
        }
        __syncthreads();
        uint32_t abase = sb + ch * 4096;
        uint32_t bbase = sb + 32768 + st * 8192;
        #pragma unroll
        for (int os = 0; os < 2; os++) {
            uint32_t colb = (uint32_t)(os * 32 + lh * 16);
            uint32_t arow = (uint32_t)(wi * 32 + l16);
            uint32_t brow = (uint32_t)(wj * 32 + l16);
            uint32_t a0[4], a1[4], b0r[4], b1r[4];
            ldsm4(a0, abase + paddr(arow, colb));
            ldsm4(a1, abase + paddr(arow + 16, colb));
            ldsm4(b0r, bbase + paddr(brow, colb));
            ldsm4(b1r, bbase + paddr(brow + 16, colb));
            #pragma unroll
            for (int mt = 0; mt < 2; mt++) {
                const uint32_t* a = mt ? a1 : a0;
                #pragma unroll
                for (int nt = 0; nt < 4; nt++) {
                    const uint32_t* bb = (nt >> 1) ? b1r : b0r;
                    int s = nt & 1;
                    mma16816h(acc + (mt * 4 + nt) * 4, a, bb[s], bb[s + 2]);
                }
            }
        }
        __syncthreads();
    }

    __half* Cs = reinterpret_cast<__half*>(gsm);
    int r4 = lane >> 2, c2 = (lane & 3) * 2;
    #pragma unroll
    for (int mt = 0; mt < 2; mt++) {
        #pragma unroll
        for (int nt = 0; nt < 4; nt++) {
            float* d = acc + (mt * 4 + nt) * 4;
            #pragma unroll
            for (int half_ = 0; half_ < 2; half_++) {
                int row = wi * 32 + mt * 16 + r4 + half_ * 8;
                int col = wj * 32 + nt * 8 + c2;
                int m = m0 + row, n = n0 + col;
                float bi = bias[m];
                float v0 = fmaxf(d[half_ * 2 + 0] - NEGC * pad[b * T_ + n] + bi, 0.f);
                float v1 = fmaxf(d[half_ * 2 + 1] - NEGC * pad[b * T_ + n + 1] + bi, 0.f);
                float* dst = &C[((long)b * O_ + m) * T_ + n];
                dst[0] = v0; dst[1] = v1;
                Cs[row * 136 + col] = __float2half(v0);
                Cs[row * 136 + col + 1] = __float2half(v1);
            }
        }
    }
    __syncthreads();
    {
        int n = tid >> 1;
        int mh = (tid & 1) * 32;
        __half hbuf[32];
        #pragma unroll
        for (int mm = 0; mm < 32; mm++) hbuf[mm] = Cs[(mh + mm) * 136 + n];
        uint4* dst = reinterpret_cast<uint4*>(&Ct[((long)b * T_ + n0 + n) * O_ + m0 + mh]);
        const uint4* srcv = reinterpret_cast<const uint4*>(hbuf);
        dst[0] = srcv[0]; dst[1] = srcv[1]; dst[2] = srcv[2]; dst[3] = srcv[3];
    }
}

// ---------------- fp16 HMMA W2 GEMM (merged via blockIdx.z) ----------------
__global__ __launch_bounds__(256) void wgemm_h_kernel(
    const __half* __restrict__ W2Rh, const __half* __restrict__ W2Qh,
    const __half* __restrict__ Rt, const __half* __restrict__ Qt,
    __half* __restrict__ OutR, __half* __restrict__ OutQ) {
    __shared__ char gsm[49152];
    uint32_t sb = smem_to_u32(gsm);
    int z = blockIdx.z;
    int sel = z >> 5, b = z & 31;
    const __half* W2h = sel ? W2Qh : W2Rh;
    const __half* Xt = sel ? Qt : Rt;
    __half* Out = sel ? OutQ : OutR;

    int n0 = blockIdx.x * 128;
    int tid = threadIdx.x, lane = tid & 31, w = tid >> 5;
    int wi = w >> 2, wj = w & 3;
    int l16 = lane & 15, lh = lane >> 4;
    const __half* Xb = Xt + ((long)b * T_ + n0) * O_;

    #pragma unroll
    for (int e = 0; e < 8; e++) {
        int idx = tid + e * 256;
        int ch = idx >> 8;
        int row = (idx & 255) >> 2;
        int cb = (idx & 3) * 16;
        cpasync16(sb + ch * 4096 + paddr(row, cb),
                  W2h + (long)row * O_ + ch * 32 + cb / 2);
    }
    CP_COMMIT();

    auto load_b = [&](int ch, int st) {
        #pragma unroll
        for (int e = 0; e < 2; e++) {
            int idx = tid + e * 256;
            int row = idx >> 2;
            int cb = (idx & 3) * 16;
            cpasync16(sb + 32768 + st * 8192 + paddr(row, cb),
                      Xb + (long)row * O_ + ch * 32 + cb / 2);
        }
    };
    load_b(0, 0);
    CP_COMMIT();

    float acc[32];
    #pragma unroll
    for (int i = 0; i < 32; i++) acc[i] = 0.f;

    for (int ch = 0; ch < 8; ch++) {
        int st = ch & 1;
        if (ch + 1 < 8) {
            load_b(ch + 1, st ^ 1);
            CP_COMMIT();
            CP_WAIT(1);
        } else {
            CP_WAIT(0);
        }
        __syncthreads();
        uint32_t abase = sb + ch * 4096;
        uint32_t bbase = sb + 32768 + st * 8192;
        #pragma unroll
        for (int os = 0; os < 2; os++) {
            uint32_t colb = (uint32_t)(os * 32 + lh * 16);
            uint32_t arow = (uint32_t)(wi * 32 + l16);
            uint32_t brow = (uint32_t)(wj * 32 + l16);
            uint32_t a0[4], a1[4], b0r[4], b1r[4];
            ldsm4(a0, abase + paddr(arow, colb));
            ldsm4(a1, abase + paddr(arow + 16, colb));
            ldsm4(b0r, bbase + paddr(brow, colb));
            ldsm4(b1r, bbase + paddr(brow + 16, colb));
            #pragma unroll
            for (int mt = 0; mt < 2; mt++) {
                const uint32_t* a = mt ? a1 : a0;
                #pragma unroll
                for (int nt = 0; nt < 4; nt++) {
                    const uint32_t* bb = (nt >> 1) ? b1r : b0r;
                    int s = nt & 1;
                    mma16816h(acc + (mt * 4 + nt) * 4, a, bb[s], bb[s + 2]);
                }
            }
        }
        __syncthreads();
    }

    int r4 = lane >> 2, c2 = (lane & 3) * 2;
    #pragma unroll
    for (int mt = 0; mt < 2; mt++) {
        #pragma unroll
        for (int nt = 0; nt < 4; nt++) {
            float* d = acc + (mt * 4 + nt) * 4;
            #pragma unroll
            for (int half_ = 0; half_ < 2; half_++) {
                int g = wi * 32 + mt * 16 + r4 + half_ * 8;
                int t = n0 + wj * 32 + nt * 8 + c2;
                __half2 v = __floats2half2_rn(d[half_ * 2], d[half_ * 2 + 1]);
                *reinterpret_cast<__half2*>(&Out[((long)b * G_ + g) * T_ + t]) = v;
            }
        }
    }
}

// ======================= fp16 HMMA F kernel (128i x 64j, 256 thr) =======================
#define FS_B 32768
#define FS_TOTAL 98304

__global__ __launch_bounds__(256, 2) void f_mma_kernel(
    const __half* __restrict__ Uk, const __half* __restrict__ Vk,
    const __half* __restrict__ Rt, const __half* __restrict__ Qt,
    __half* __restrict__ Ft, const int* __restrict__ jmin, const int* __restrict__ imax) {
    extern __shared__ char sm[];
    uint32_t sb = smem_to_u32(sm);
    int tid = threadIdx.x, lane = tid & 31, w = tid >> 5;
    int wi = w >> 1, wj = w & 1;
    int b = blockIdx.z, i0 = blockIdx.y * 128, j0 = blockIdx.x * 64;
    int l16 = lane & 15, lh = lane >> 4;

    if (i0 >= imax[b]) return;

    if (j0 >= jmin[b]) {
        int j = tid >> 2, iq = (tid & 3) * 32;
        uint4 z4 = make_uint4(0, 0, 0, 0);
        uint4* dst = reinterpret_cast<uint4*>(&Ft[((long)b * T_ + j0 + j) * T_ + i0 + iq]);
        dst[0] = z4; dst[1] = z4; dst[2] = z4; dst[3] = z4;
        return;
    }

    const __half* apt[2] = {Uk, Vk};
    const __half* bpt[2] = {Rt, Qt};

    #pragma unroll
    for (int arr = 0; arr < 2; arr++) {
        const __half* src = bpt[arr] + ((long)b * T_ + j0) * O_;
        #pragma unroll
        for (int e = 0; e < 8; e++) {
            int idx = tid + e * 256;
            int ch = idx >> 8;
            int row = (idx & 255) >> 2;
            int cb = (idx & 3) * 16;
            const void* g = src + (long)row * O_ + ch * 32 + cb / 2;
            cpasync16(sb + FS_B + arr * 32768 + ch * 4096 + paddr(row, cb), g);
        }
    }
    CP_COMMIT();

    auto load_a = [&](int cu, int st) {
        int k = cu >> 3, ch = cu & 7;
        #pragma unroll
        for (int arr = 0; arr < 2; arr++) {
            const __half* src = apt[arr] + ((long)k * T_ + i0) * O_ + ch * 32;
            #pragma unroll
            for (int e = 0; e < 2; e++) {
                int idx = tid + e * 256;
                int row = idx >> 2;
                int cb = (idx & 3) * 16;
                const void* g = src + (long)row * O_ + cb / 2;
                cpasync16(sb + st * 16384 + arr * 8192 + paddr(row, cb), g);
            }
        }
    };

    load_a(0, 0);
    CP_COMMIT();

    float f[32], d1[32], d2[32];
    #pragma unroll
    for (int i = 0; i < 32; i++) { f[i] = 0.f; d1[i] = 0.f; d2[i] = 0.f; }

    for (int cu = 0; cu < 64; cu++) {
        int st = cu & 1, ch = cu & 7;
        if (cu + 1 < 64) {
            load_a(cu + 1, (cu + 1) & 1);
            CP_COMMIT();
            CP_WAIT(1);
        } else {
            CP_WAIT(0);
        }
        __syncthreads();

        uint32_t abase = sb + st * 16384;
        #pragma unroll
        for (int os = 0; os < 2; os++) {
            uint32_t colb = (uint32_t)(os * 32 + lh * 16);
            uint32_t arow = (uint32_t)(wi * 32 + l16);
            uint32_t brow = (uint32_t)(wj * 32 + l16);
            {
                uint32_t a0[4], a1[4], b0r[4], b1r[4];
                ldsm4(a0, abase + 0 * 8192 + paddr(arow, colb));
                ldsm4(a1, abase + 0 * 8192 + paddr(arow + 16, colb));
                uint32_t bb0 = sb + FS_B + 0 * 32768 + ch * 4096;
                ldsm4(b0r, bb0 + paddr(brow, colb));
                ldsm4(b1r, bb0 + paddr(brow + 16, colb));
                #pragma unroll
                for (int mt = 0; mt < 2; mt++) {
                    const uint32_t* a = mt ? a1 : a0;
                    #pragma unroll
                    for (int nt = 0; nt < 4; nt++) {
                        const uint32_t* bb = (nt >> 1) ? b1r : b0r;
                        int s = nt & 1;
                        mma16816h(d1 + (mt * 4 + nt) * 4, a, bb[s], bb[s + 2]);
                    }
                }
            }
            {
                uint32_t a0[4], a1[4], b0r[4], b1r[4];
                ldsm4(a0, abase + 1 * 8192 + paddr(arow, colb));
                ldsm4(a1, abase + 1 * 8192 + paddr(arow + 16, colb));
                uint32_t bb1 = sb + FS_B + 1 * 32768 + ch * 4096;
                ldsm4(b0r, bb1 + paddr(brow, colb));
                ldsm4(b1r, bb1 + paddr(brow + 16, colb));
                #pragma unroll
                for (int mt = 0; mt < 2; mt++) {
                    const uint32_t* a = mt ? a1 : a0;
                    #pragma unroll
                    for (int nt = 0; nt < 4; nt++) {
                        const uint32_t* bb = (nt >> 1) ? b1r : b0r;
                        int s = nt & 1;
                        mma16816h(d2 + (mt * 4 + nt) * 4, a, bb[s], bb[s + 2]);
                    }
                }
            }
        }
        if (ch == 7) {
            #pragma unroll
            for (int i = 0; i < 32; i++) {
                f[i] += d1[i] * d2[i];
                d1[i] = 0.f; d2[i] = 0.f;
            }
        }
        __syncthreads();
    }

    __half* Fs16 = reinterpret_cast<__half*>(sm);
    int r4 = lane >> 2, c2 = (lane & 3) * 2;
    #pragma unroll
    for (int mt = 0; mt < 2; mt++) {
        #pragma unroll
        for (int nt = 0; nt < 4; nt++) {
            float* d = f + (mt * 4 + nt) * 4;
            #pragma unroll
            for (int hh = 0; hh < 2; hh++) {
                int i_l = wi * 32 + mt * 16 + r4 + hh * 8;
                int j_l = wj * 32 + nt * 8 + c2;
                *reinterpret_cast<__half2*>(&Fs16[i_l * 72 + j_l]) =
                    __floats2half2_rn(d[hh * 2], d[hh * 2 + 1]);
            }
        }
    }
    __syncthreads();
    {
        int j = tid >> 2, iq = (tid & 3) * 32;
        __half hbuf[32];
        #pragma unroll
        for (int ii = 0; ii < 32; ii++) hbuf[ii] = Fs16[(iq + ii) * 72 + j];
        uint4* dst = reinterpret_cast<uint4*>(&Ft[((long)b * T_ + j0 + j) * T_ + i0 + iq]);
        const uint4* s4 = reinterpret_cast<const uint4*>(hbuf);
        dst[0] = s4[0]; dst[1] = s4[1]; dst[2] = s4[2]; dst[3] = s4[3];
    }
}

// ---------------- fp16 HMMA fused M + d kernel (merged via blockIdx.z) ----------------
__global__ __launch_bounds__(128) void md_h_kernel(
    const __half* __restrict__ WRb, const __half* __restrict__ WQb,
    const __half* __restrict__ Ft,
    const float* __restrict__ wmv, const float* __restrict__ wmq,
    const float* __restrict__ pq, const float* __restrict__ pv,
    float* __restrict__ d1, float* __restrict__ d2,
    const int* __restrict__ l1, const int* __restrict__ l2) {
    __shared__ char msm[16384];
    __shared__ float red[64][65];
    __shared__ float p2[2][64];
    uint32_t sb = smem_to_u32(msm);
    int sel = blockIdx.z;
    int b = blockIdx.y, c0 = blockIdx.x * 64;
    const __half* Bias = sel ? WQb : WRb;
    const __half* Mul  = sel ? WRb : WQb;
    const float* wv = sel ? wmq : wmv;
    const float* pad = sel ? pv : pq;
    float* d = sel ? d2 : d1;
    const int* lencol = sel ? l2 : l1;
    const int* lenmul = sel ? l1 : l2;

    int tid = threadIdx.x, lane = tid & 31, w_ = tid >> 5;
    int wg = w_ >> 1, wc = w_ & 1;
    int l16 = lane & 15, lh = lane >> 4;

    if (c0 >= lencol[b]) {
        if (tid < 64) d[b * T_ + c0 + tid] = -NEGC;
        return;
    }
    int nch = ((lenmul[b] + 31) & ~31) >> 5;
    const __half* Mb = Mul + (long)b * G_ * T_;
    const __half* Fb = Ft + ((long)b * T_ + c0) * T_;

    auto load_ch = [&](int ch, int st) {
        #pragma unroll
        for (int e = 0; e < 2; e++) {
            int idx = tid + e * 128;
            int row = idx >> 2, cb = (idx & 3) * 16;
            cpasync16(sb + st * 8192 + paddr(row, cb), Mb + (long)row * T_ + ch * 32 + cb / 2);
        }
        #pragma unroll
        for (int e = 0; e < 2; e++) {
            int idx = tid + e * 128;
            int row = idx >> 2, cb = (idx & 3) * 16;
            cpasync16(sb + st * 8192 + 4096 + paddr(row, cb), Fb + (long)row * T_ + ch * 32 + cb / 2);
        }
    };
    load_ch(0, 0);
    CP_COMMIT();

    float acc[32];
    #pragma unroll
    for (int i = 0; i < 32; i++) acc[i] = 0.f;

    for (int ch = 0; ch < nch; ch++) {
        int st = ch & 1;
        if (ch + 1 < nch) {
            load_ch(ch + 1, st ^ 1);
            CP_COMMIT();
            CP_WAIT(1);
        } else {
            CP_WAIT(0);
        }
        __syncthreads();
        uint32_t ab = sb + st * 8192, bb_ = ab + 4096;
        #pragma unroll
        for (int os = 0; os < 2; os++) {
            uint32_t colb = (uint32_t)(os * 32 + lh * 16);
            uint32_t arow = (uint32_t)(wg * 32 + l16);
            uint32_t brow = (uint32_t)(wc * 32 + l16);
            uint32_t a0[4], a1[4], b0r[4], b1r[4];
            ldsm4(a0, ab + paddr(arow, colb));
            ldsm4(a1, ab + paddr(arow + 16, colb));
            ldsm4(b0r, bb_ + paddr(brow, colb));
            ldsm4(b1r, bb_ + paddr(brow + 16, colb));
            #pragma unroll
            for (int mt = 0; mt < 2; mt++) {
                const uint32_t* a = mt ? a1 : a0;
                #pragma unroll
                for (int nt = 0; nt < 4; nt++) {
                    const uint32_t* bb = (nt >> 1) ? b1r : b0r;
                    int s = nt & 1;
                    mma16816h(acc + (mt * 4 + nt) * 4, a, bb[s], bb[s + 2]);
                }
            }
        }
        __syncthreads();
    }

    int r4 = lane >> 2, c2 = (lane & 3) * 2;
    #pragma unroll
    for (int mt = 0; mt < 2; mt++) {
        #pragma unroll
        for (int nt = 0; nt < 4; nt++) {
            float* dd = acc + (mt * 4 + nt) * 4;
            #pragma unroll
            for (int hh = 0; hh < 2; hh++) {
                int g = wg * 32 + mt * 16 + r4 + hh * 8;
                int col = wc * 32 + nt * 8 + c2;
                float wgt = wv[g];
                float bi0 = __half2float(Bias[(long)b * G_ * T_ + g * T_ + c0 + col]);
                float bi1 = __half2float(Bias[(long)b * G_ * T_ + g * T_ + c0 + col + 1]);
                red[g][col]     = wgt * fmaxf(dd[hh * 2 + 0] + bi0, 0.f);
                red[g][col + 1] = wgt * fmaxf(dd[hh * 2 + 1] + bi1, 0.f);
            }
        }
    }
    __syncthreads();
    {
        int col = tid & 63, h = tid >> 6;
        float s = 0.f;
        #pragma unroll
        for (int g = 0; g < 32; g++) s += red[h * 32 + g][col];
        p2[h][col] = s;
    }
    __syncthreads();
    if (tid < 64)
        d[b * T_ + c0 + tid] = p2[0][tid] + p2[1][tid] - NEGC * pad[b * T_ + c0 + tid];
}

// ---------------- softmax ----------------
__global__ void softmax_kernel(const float* __restrict__ d1, const float* __restrict__ d2,
                               float* __restrict__ g1, float* __restrict__ g2) {
    int b = blockIdx.x;
    const float* d = blockIdx.y ? d2 : d1;
    float* g = blockIdx.y ? g2 : g1;
    int t = threadIdx.x;
    float v = d[b * T_ + t];
    __shared__ float red[16];
    float m = v;
    #pragma unroll
    for (int o = 16; o; o >>= 1) m = fmaxf(m, __shfl_xor_sync(0xffffffffu, m, o));
    if ((t & 31) == 0) red[t >> 5] = m;
    __syncthreads();
    if (t < 32) {
        float x = (t < 16) ? red[t] : -3.4e38f;
        #pragma unroll
        for (int o = 8; o; o >>= 1) x = fmaxf(x, __shfl_xor_sync(0xffffffffu, x, o));
        if (t == 0) red[0] = x;
    }
    __syncthreads();
    float mx = red[0];
    __syncthreads();
    float e = expf(v - mx);
    float s = e;
    #pragma unroll
    for (int o = 16; o; o >>= 1) s += __shfl_xor_sync(0xffffffffu, s, o);
    if ((t & 31) == 0) red[t >> 5] = s;
    __syncthreads();
    if (t < 32) {
        float x = (t < 16) ? red[t] : 0.f;
        #pragma unroll
        for (int o = 8; o; o >>= 1) x += __shfl_xor_sync(0xffffffffu, x, o);
        if (t == 0) red[0] = x;
    }
    __syncthreads();
    g[b * T_ + t] = e / red[0];
}

// ---------------- final reduction ----------------
__global__ void final_kernel(const float* __restrict__ R, const float* __restrict__ Q,
                             const float* __restrict__ gv, const float* __restrict__ gq,
                             float* __restrict__ out) {
    int b = blockIdx.x;
    __shared__ float sgv[T_], sgq[T_];
    int tid = threadIdx.x;
    sgv[tid] = gv[b * T_ + tid];
    sgq[tid] = gq[b * T_ + tid];
    __syncthreads();
    int o = tid & 255;
    int h = tid >> 8;
    const float* Rb = R + (long)b * O_ * T_;
    const float* Qb = Q + (long)b * O_ * T_;
    float tr = 0.f, lg = 0.f;
    #pragma unroll 4
    for (int t = h * 256; t < h * 256 + 256; t++) {
        tr += sgv[t] * Rb[t * O_ + o];
        lg += sgq[t] * Qb[t * O_ + o];
    }
    __shared__ float str[2][256], slg[2][256];
    str[h][o] = tr;
    slg[h][o] = lg;
    __syncthreads();
    if (h == 0) out[b * O_ + o] = (str[0][o] + str[1][o]) * (slg[0][o] + slg[1][o]);
}

// ---------------- launcher ----------------
extern "C" void kernel_launch(void* const* d_in, const int* in_sizes, int n_in,
                              void* d_out, int out_size) {
    const float* x0  = (const float*)d_in[0];
    const float* x1  = (const float*)d_in[1];
    const unsigned char* qm = (const unsigned char*)d_in[2];
    const unsigned char* vm = (const unsigned char*)d_in[3];
    const float* W_R = (const float*)d_in[4];
    const float* W_Q = (const float*)d_in[5];
    const float* br  = (const float*)d_in[6];
    const float* bq  = (const float*)d_in[7];
    const float* U   = (const float*)d_in[8];
    const float* V   = (const float*)d_in[9];
    const float* W2R = (const float*)d_in[10];
    const float* W2Q = (const float*)d_in[11];
    const float* wmv = (const float*)d_in[12];
    const float* wmq = (const float*)d_in[13];
    float* out = (float*)d_out;

    float *pR, *pQ, *pd1, *pd2, *pg1, *pg2, *ppq, *ppv;
    int *pl1, *pl2, *pjm, *pim;
    __half *pUk, *pVk, *pRt, *pQt, *pWRh, *pWQh, *pW2Rh, *pW2Qh, *px0t, *px1t, *pFt, *pWRb, *pWQb;
    cudaGetSymbolAddress((void**)&pR,  g_R);
    cudaGetSymbolAddress((void**)&pQ,  g_Q);
    cudaGetSymbolAddress((void**)&pd1, g_d1);
    cudaGetSymbolAddress((void**)&pd2, g_d2);
    cudaGetSymbolAddress((void**)&pg1, g_g1);
    cudaGetSymbolAddress((void**)&pg2, g_g2);
    cudaGetSymbolAddress((void**)&ppq, g_pq);
    cudaGetSymbolAddress((void**)&ppv, g_pv);
    cudaGetSymbolAddress((void**)&pl1, g_len1);
    cudaGetSymbolAddress((void**)&pl2, g_len2);
    cudaGetSymbolAddress((void**)&pjm, g_jmin);
    cudaGetSymbolAddress((void**)&pim, g_imax);
    cudaGetSymbolAddress((void**)&pUk, g_Uk);
    cudaGetSymbolAddress((void**)&pVk, g_Vk);
    cudaGetSymbolAddress((void**)&pRt, g_Rt);
    cudaGetSymbolAddress((void**)&pQt, g_Qt);
    cudaGetSymbolAddress((void**)&pWRh, g_WRh);
    cudaGetSymbolAddress((void**)&pWQh, g_WQh);
    cudaGetSymbolAddress((void**)&pW2Rh, g_W2Rh);
    cudaGetSymbolAddress((void**)&pW2Qh, g_W2Qh);
    cudaGetSymbolAddress((void**)&px0t, g_x0t);
    cudaGetSymbolAddress((void**)&px1t, g_x1t);
    cudaGetSymbolAddress((void**)&pFt, g_Ft);
    cudaGetSymbolAddress((void**)&pWRb, g_WRb);
    cudaGetSymbolAddress((void**)&pWQb, g_WQb);

    static cudaStream_t s2 = nullptr;
    static cudaEvent_t evFork = nullptr, evX = nullptr, evG = nullptr, evW = nullptr;
    static bool init_done = false;
    if (!init_done) {
        cudaFuncSetAttribute(f_mma_kernel, cudaFuncAttributeMaxDynamicSharedMemorySize, FS_TOTAL);
        cudaFuncSetAttribute(gemm_rq_h_kernel, cudaFuncAttributeMaxDynamicSharedMemorySize, 49152);
        cudaStreamCreateWithFlags(&s2, cudaStreamNonBlocking);
        cudaEventCreateWithFlags(&evFork, cudaEventDisableTiming);
        cudaEventCreateWithFlags(&evX, cudaEventDisableTiming);
        cudaEventCreateWithFlags(&evG, cudaEventDisableTiming);
        cudaEventCreateWithFlags(&evW, cudaEventDisableTiming);
        init_done = true;
    }

    // fork: convX on s2 concurrent with lens+convs on default stream
    cudaEventRecord(evFork, 0);
    cudaStreamWaitEvent(s2, evFork, 0);
    convX_kernel<<<dim3(T_ / 32, D_ / 32, 2 * B_), dim3(32, 8), 0, s2>>>(x0, x1, px0t, px1t);
    cudaEventRecord(evX, s2);

    lens_kernel<<<B_, T_>>>(qm, vm, ppq, ppv, pl1, pl2, pjm, pim);
    convs_kernel<<<(KF_ * T_ * O_ + 255) / 256, 256>>>(
        U, V, W_R, W_Q, W2R, W2Q, pUk, pVk, pWRh, pWQh, pW2Rh, pW2Qh);

    cudaStreamWaitEvent(0, evX, 0);
    gemm_rq_h_kernel<<<dim3(T_ / 128, O_ / 64, 2 * B_), 256, 49152>>>(
        pWRh, pWQh, px0t, px1t, pR, pQ, pRt, pQt, br, bq, ppq, ppv, pl1, pl2);
    cudaEventRecord(evG, 0);

    // wgemm on s2 overlaps f_mma on default stream
    cudaStreamWaitEvent(s2, evG, 0);
    wgemm_h_kernel<<<dim3(T_ / 128, 1, 2 * B_), 256, 0, s2>>>(
        pW2Rh, pW2Qh, pRt, pQt, pWRb, pWQb);
    cudaEventRecord(evW, s2);

    f_mma_kernel<<<dim3(T_ / 64, T_ / 128, B_), 256, FS_TOTAL>>>(
        pUk, pVk, pRt, pQt, pFt, pjm, pim);

    cudaStreamWaitEvent(0, evW, 0);
    md_h_kernel<<<dim3(T_ / 64, B_, 2), 128>>>(
        pWRb, pWQb, pFt, wmv, wmq, ppq, ppv, pd1, pd2, pl1, pl2);

    softmax_kernel<<<dim3(B_, 2), T_>>>(pd1, pd2, pg1, pg2);

    final_kernel<<<B_, T_>>>(pR, pQ, pg1, pg2, out);
}